// round 4
// baseline (speedup 1.0000x reference)
#include <cuda_runtime.h>
#include <cuda_bf16.h>
#include <cstdint>
#include <math.h>

#define NT   16384
#define GN   128
#define DD   128
#define HN   4
#define DHD  32
#define NBLK 10
#define MAXL 256
#define EPSV 1e-5f

typedef __nv_bfloat16 bf16;

// ---------------- scratch ----------------
__device__ float g_x  [NT * DD];          // residual stream (fp32)
__device__ float g_qkv[NT * 3 * DD];      // qkv (fp32)
__device__ bf16  g_yh [NT * DD];          // LN output hi/lo
__device__ bf16  g_yl [NT * DD];
__device__ bf16  g_ah [NT * DD];          // attention output hi/lo
__device__ bf16  g_al [NT * DD];
__device__ bf16  g_mh [NT * 4 * DD];      // MLP hidden hi/lo
__device__ bf16  g_ml [NT * 4 * DD];
__device__ float g_bn_mean[16];
__device__ float g_bn_rstd[16];
__device__ int   g_seg[GN + 1];

// bf16 hi/lo weights, transposed to [N][K]
__device__ bf16 g_wq_hi [NBLK * 384 * 128];
__device__ bf16 g_wq_lo [NBLK * 384 * 128];
__device__ bf16 g_wo_hi [NBLK * 128 * 128];
__device__ bf16 g_wo_lo [NBLK * 128 * 128];
__device__ bf16 g_wm1_hi[NBLK * 512 * 128];
__device__ bf16 g_wm1_lo[NBLK * 512 * 128];
__device__ bf16 g_wm2_hi[NBLK * 128 * 512];
__device__ bf16 g_wm2_lo[NBLK * 128 * 512];

// ---------------- asm helpers ----------------
__device__ __forceinline__ uint32_t smem_u32(const void* p) {
    uint32_t a;
    asm("{ .reg .u64 t; cvta.to.shared.u64 t, %1; cvt.u32.u64 %0, t; }" : "=r"(a) : "l"(p));
    return a;
}
__device__ __forceinline__ void cp16(uint32_t dst, const void* src) {
    asm volatile("cp.async.cg.shared.global [%0], [%1], 16;" :: "r"(dst), "l"(src));
}
#define CP_COMMIT() asm volatile("cp.async.commit_group;" ::: "memory")
#define CP_WAIT(n)  asm volatile("cp.async.wait_group %0;" :: "n"(n) : "memory")

__device__ __forceinline__ void ldm_x4(uint32_t r[4], uint32_t a) {
    asm volatile("ldmatrix.sync.aligned.m8n8.x4.shared.b16 {%0,%1,%2,%3}, [%4];"
                 : "=r"(r[0]), "=r"(r[1]), "=r"(r[2]), "=r"(r[3]) : "r"(a));
}
__device__ __forceinline__ void ldm_x4_t(uint32_t r[4], uint32_t a) {
    asm volatile("ldmatrix.sync.aligned.m8n8.x4.trans.shared.b16 {%0,%1,%2,%3}, [%4];"
                 : "=r"(r[0]), "=r"(r[1]), "=r"(r[2]), "=r"(r[3]) : "r"(a));
}
__device__ __forceinline__ void mma_bf16(float c[4], const uint32_t a[4],
                                         uint32_t b0, uint32_t b1) {
    asm volatile(
        "mma.sync.aligned.m16n8k16.row.col.f32.bf16.bf16.f32 "
        "{%0,%1,%2,%3}, {%4,%5,%6,%7}, {%8,%9}, {%0,%1,%2,%3};"
        : "+f"(c[0]), "+f"(c[1]), "+f"(c[2]), "+f"(c[3])
        : "r"(a[0]), "r"(a[1]), "r"(a[2]), "r"(a[3]), "r"(b0), "r"(b1));
}

__device__ __forceinline__ void split_bf16(float v, bf16& hi, bf16& lo) {
    hi = __float2bfloat16(v);
    lo = __float2bfloat16(v - __bfloat162float(hi));
}
__device__ __forceinline__ uint32_t pack2(bf16 a, bf16 b) {
    __nv_bfloat162 t = {a, b};
    return *(uint32_t*)&t;
}
__device__ __forceinline__ float fast_gelu(float u) {
    float z = 0.7978845608028654f * (u + 0.044715f * u * u * u);
    float t = 1.f - 2.f / (__expf(2.f * z) + 1.f);
    return 0.5f * u * (1.f + t);
}

// ---------------- BN batch stats ----------------
__global__ void bn_stats_kernel(const float* __restrict__ s, const float* __restrict__ v) {
    int f = blockIdx.x, t = threadIdx.x;
    float sum = 0.f, sq = 0.f;
    for (int i = t; i < NT; i += 256) {
        float x = (f < 13) ? s[i * 13 + f] : v[i * 3 + (f - 13)];
        sum += x; sq += x * x;
    }
    __shared__ float rs[256], rq[256];
    rs[t] = sum; rq[t] = sq;
    __syncthreads();
    for (int st = 128; st > 0; st >>= 1) {
        if (t < st) { rs[t] += rs[t + st]; rq[t] += rq[t + st]; }
        __syncthreads();
    }
    if (t == 0) {
        float m = rs[0] * (1.f / NT);
        float var = rq[0] * (1.f / NT) - m * m;
        g_bn_mean[f] = m;
        g_bn_rstd[f] = rsqrtf(var + EPSV);
    }
}

// ---------------- segment offsets ----------------
__global__ void seg_kernel(const int* __restrict__ bidx) {
    int g = threadIdx.x;
    if (g > GN) return;
    int lo = 0, hi = NT;
    while (lo < hi) {
        int mid = (lo + hi) >> 1;
        if (bidx[mid] < g) lo = mid + 1; else hi = mid;
    }
    g_seg[g] = lo;
}

// ---------------- BN + embed ----------------
__global__ void embed_kernel(const float* __restrict__ s, const float* __restrict__ v,
                             const float* __restrict__ gamma, const float* __restrict__ beta,
                             const float* __restrict__ w_in, const float* __restrict__ b_in) {
    int row = blockIdx.x, t = threadIdx.x;
    __shared__ float xn[16];
    if (t < 16) {
        float x = (t < 13) ? s[row * 13 + t] : v[row * 3 + (t - 13)];
        xn[t] = (x - g_bn_mean[t]) * g_bn_rstd[t] * gamma[t] + beta[t];
    }
    __syncthreads();
    float acc = b_in[t];
#pragma unroll
    for (int k = 0; k < 16; k++) acc += xn[k] * w_in[k * DD + t];
    g_x[row * DD + t] = acc;
}

// ---------------- LayerNorm: warp per row -> hi/lo bf16 ----------------
__global__ __launch_bounds__(256)
void ln_kernel(const float* __restrict__ gam, const float* __restrict__ bet) {
    int w = threadIdx.x >> 5, lane = threadIdx.x & 31;
    int row = blockIdx.x * 8 + w;
    const float* xp = g_x + (size_t)row * DD;
    float4 xv = *(const float4*)(xp + lane * 4);
    float s = xv.x + xv.y + xv.z + xv.w;
    float sq = xv.x * xv.x + xv.y * xv.y + xv.z * xv.z + xv.w * xv.w;
#pragma unroll
    for (int o = 16; o; o >>= 1) {
        s  += __shfl_xor_sync(0xffffffffu, s,  o);
        sq += __shfl_xor_sync(0xffffffffu, sq, o);
    }
    float m = s * (1.f / DD);
    float var = sq * (1.f / DD) - m * m;
    float r = rsqrtf(var + EPSV);
    float4 gv = *(const float4*)(gam + lane * 4);
    float4 bv = *(const float4*)(bet + lane * 4);
    float o0 = (xv.x - m) * r * gv.x + bv.x;
    float o1 = (xv.y - m) * r * gv.y + bv.y;
    float o2 = (xv.z - m) * r * gv.z + bv.z;
    float o3 = (xv.w - m) * r * gv.w + bv.w;
    bf16 h[4], l[4];
    split_bf16(o0, h[0], l[0]); split_bf16(o1, h[1], l[1]);
    split_bf16(o2, h[2], l[2]); split_bf16(o3, h[3], l[3]);
    *(uint2*)(g_yh + (size_t)row * DD + lane * 4) = *(uint2*)h;
    *(uint2*)(g_yl + (size_t)row * DD + lane * 4) = *(uint2*)l;
}

// ---------------- weight prep ----------------
__global__ void wprep_kernel(const float* __restrict__ w, bf16* __restrict__ whi,
                             bf16* __restrict__ wlo, int K, int N) {
    int idx = blockIdx.x * 256 + threadIdx.x;
    int total = NBLK * N * K;
    if (idx >= total) return;
    int k = idx % K;
    int n = (idx / K) % N;
    int b = idx / (K * N);
    float x = w[(size_t)b * K * N + (size_t)k * N + n];
    bf16 hi, lo;
    split_bf16(x, hi, lo);
    whi[idx] = hi;
    wlo[idx] = lo;
}

// ---------------- mma.sync GEMM (unchanged from R3) ----------------
#define STG 24576
#define OFF_AH 0
#define OFF_AL 6144
#define OFF_BH 12288
#define OFF_BL 18432
#define GEMM_SMEM (2 * STG)

template <int FUSE>
__global__ __launch_bounds__(256)
void gemm_mma(const bf16* __restrict__ Ahi, const bf16* __restrict__ Alo,
              const bf16* __restrict__ Bhi, const bf16* __restrict__ Blo,
              const float* __restrict__ bias, const float* __restrict__ R,
              float* __restrict__ C, bf16* __restrict__ Chi, bf16* __restrict__ Clo,
              int K, int Nc) {
    extern __shared__ char smem[];
    uint32_t sb = smem_u32(smem);
    int tid = threadIdx.x, lane = tid & 31, wid = tid >> 5;
    int wm = wid & 3, wn = wid >> 2;
    int m0 = blockIdx.y * 128, n0 = blockIdx.x * 128;

    int ldrow = tid >> 1, ldhalf = tid & 1;
    const bf16* pAh = Ahi + (size_t)(m0 + ldrow) * K + ldhalf * 8;
    const bf16* pAl = Alo + (size_t)(m0 + ldrow) * K + ldhalf * 8;
    const bf16* pBh = Bhi + (size_t)(n0 + ldrow) * K + ldhalf * 8;
    const bf16* pBl = Blo + (size_t)(n0 + ldrow) * K + ldhalf * 8;
    uint32_t dstb = sb + ldrow * 48 + ldhalf * 16;

    float acc[2][8][4];
#pragma unroll
    for (int i = 0; i < 2; i++)
#pragma unroll
        for (int j = 0; j < 8; j++)
#pragma unroll
            for (int q = 0; q < 4; q++) acc[i][j][q] = 0.f;

    int nsteps = K >> 4;
    {
        uint32_t d = dstb;
        cp16(d + OFF_AH, pAh);
        cp16(d + OFF_AL, pAl);
        cp16(d + OFF_BH, pBh);
        cp16(d + OFF_BL, pBl);
        CP_COMMIT();
    }

    uint32_t a_off = (uint32_t)((wm * 32 + (lane & 15)) * 48 + (lane >> 4) * 16);
    uint32_t b_row = (uint32_t)(wn * 64 + (lane & 7) + ((lane >> 4) << 3));
    uint32_t b_off = b_row * 48 + (((lane >> 3) & 1) << 4);

    for (int c = 0; c < nsteps; c++) {
        if (c + 1 < nsteps) {
            int k0 = (c + 1) << 4;
            uint32_t d = dstb + ((c + 1) & 1) * STG;
            cp16(d + OFF_AH, pAh + k0);
            cp16(d + OFF_AL, pAl + k0);
            cp16(d + OFF_BH, pBh + k0);
            cp16(d + OFF_BL, pBl + k0);
            CP_COMMIT();
            CP_WAIT(1);
        } else {
            CP_WAIT(0);
        }
        __syncthreads();

        uint32_t sA = sb + (c & 1) * STG;
        uint32_t sB = sA + OFF_BH;

        uint32_t ah[2][4], al[2][4];
#pragma unroll
        for (int mt = 0; mt < 2; mt++) {
            uint32_t addr = sA + a_off + mt * 16 * 48;
            ldm_x4(ah[mt], addr + OFF_AH);
            ldm_x4(al[mt], addr + OFF_AL);
        }
        uint32_t bh[8][2], bl[8][2];
#pragma unroll
        for (int g4 = 0; g4 < 4; g4++) {
            uint32_t addr = sB + b_off + g4 * 16 * 48;
            uint32_t t4[4];
            ldm_x4(t4, addr);
            bh[g4 * 2][0] = t4[0]; bh[g4 * 2][1] = t4[1];
            bh[g4 * 2 + 1][0] = t4[2]; bh[g4 * 2 + 1][1] = t4[3];
            ldm_x4(t4, addr + (OFF_BL - OFF_BH));
            bl[g4 * 2][0] = t4[0]; bl[g4 * 2][1] = t4[1];
            bl[g4 * 2 + 1][0] = t4[2]; bl[g4 * 2 + 1][1] = t4[3];
        }
#pragma unroll
        for (int mt = 0; mt < 2; mt++)
#pragma unroll
            for (int nt = 0; nt < 8; nt++) {
                mma_bf16(acc[mt][nt], ah[mt], bh[nt][0], bh[nt][1]);
                mma_bf16(acc[mt][nt], ah[mt], bl[nt][0], bl[nt][1]);
                mma_bf16(acc[mt][nt], al[mt], bh[nt][0], bh[nt][1]);
            }
        __syncthreads();
    }

    int lane4 = lane >> 2, lanem = (lane & 3) * 2;
#pragma unroll
    for (int mt = 0; mt < 2; mt++) {
#pragma unroll
        for (int nt = 0; nt < 8; nt++) {
            int col = n0 + wn * 64 + nt * 8 + lanem;
            int r0 = m0 + wm * 32 + mt * 16 + lane4;
            float b0 = bias[col], b1 = bias[col + 1];
#pragma unroll
            for (int half = 0; half < 2; half++) {
                int r = r0 + half * 8;
                float v0 = acc[mt][nt][half * 2 + 0] + b0;
                float v1 = acc[mt][nt][half * 2 + 1] + b1;
                size_t o = (size_t)r * Nc + col;
                if (FUSE == 1) {
                    float2 rr = *(const float2*)(R + o);
                    v0 += rr.x; v1 += rr.y;
                }
                if (FUSE == 2) {
                    v0 = fast_gelu(v0);
                    v1 = fast_gelu(v1);
                    bf16 h0, l0, h1, l1;
                    split_bf16(v0, h0, l0);
                    split_bf16(v1, h1, l1);
                    *(uint32_t*)(Chi + o) = pack2(h0, h1);
                    *(uint32_t*)(Clo + o) = pack2(l0, l1);
                } else {
                    float2 ov = {v0, v1};
                    *(float2*)(C + o) = ov;
                }
            }
        }
    }
}

// ---------------- tensor-core segment attention ----------------
// CTA per (graph, head), 4 warps. K/V bf16 hi/lo in smem (80B rows).
// Warp handles m16 query tiles strided by 4. S via compensated mma -> fp32 smem,
// 2-pass softmax -> P hi/lo bf16 -> compensated mma with ldmatrix.trans V.
#define AT_KVB   20480                       // 256 rows * 80B
#define AT_WPB   33344                       // Sbuf 16448 + Ph 8448 + Pl 8448
#define AT_SMEM  (4 * AT_KVB + 4 * AT_WPB)   // 215296

__global__ __launch_bounds__(128)
void attn_tc() {
    extern __shared__ char sm[];
    int g = blockIdx.x, h = blockIdx.y;
    int start = g_seg[g];
    int cnt = g_seg[g + 1] - start;
    if (cnt <= 0) return;
    if (cnt > MAXL) cnt = MAXL;
    int tid = threadIdx.x, lane = tid & 31, wid = tid >> 5;
    int tiles = (cnt + 15) >> 4;
    int ncols = tiles << 4;

    bf16* sKh = (bf16*)sm;
    bf16* sKl = (bf16*)(sm + AT_KVB);
    bf16* sVh = (bf16*)(sm + 2 * AT_KVB);
    bf16* sVl = (bf16*)(sm + 3 * AT_KVB);
    char* wb = sm + 4 * AT_KVB + wid * AT_WPB;
    float* Sbuf = (float*)wb;                  // [16][257] fp32
    bf16* Ph = (bf16*)(wb + 16448);            // [16][264] bf16 (528B rows)
    bf16* Pl = (bf16*)(wb + 16448 + 8448);

    // stage K/V (pads zeroed)
    for (int idx = tid; idx < (ncols << 5); idx += 128) {
        int j = idx >> 5, d = idx & 31;
        bf16 kh, kl, vh, vl;
        if (j < cnt) {
            const float* base = g_qkv + (size_t)(start + j) * 384 + h * 32 + d;
            split_bf16(base[128], kh, kl);
            split_bf16(base[256], vh, vl);
        } else {
            kh = kl = vh = vl = __float2bfloat16(0.f);
        }
        sKh[j * 40 + d] = kh; sKl[j * 40 + d] = kl;
        sVh[j * 40 + d] = vh; sVl[j * 40 + d] = vl;
    }
    __syncthreads();

    uint32_t aKh = smem_u32(sKh), aKl = smem_u32(sKl);
    uint32_t aVh = smem_u32(sVh), aVl = smem_u32(sVl);
    uint32_t aPh = smem_u32(Ph),  aPl = smem_u32(Pl);

    const float scale = 0.17677669529663687f;
    int fr = lane >> 2, fc = (lane & 3) * 2;   // frag row/col bases
    // K/V ldmatrix lane offsets
    uint32_t kb_row = (uint32_t)((lane & 7) + ((lane >> 4) << 3));
    uint32_t kb_off = kb_row * 80 + (((lane >> 3) & 1) << 4);
    uint32_t vt_off = (uint32_t)((lane & 15) * 80 + ((lane >> 4) << 4));

    for (int mt = wid; mt < tiles; mt += 4) {
        int m0t = mt << 4;
        // ---- Q frags direct from global (scaled, hi/lo, clamped rows) ----
        uint32_t qh[2][4], ql[2][4];
        {
            int r1 = start + m0t + fr, r2 = r1 + 8;
            if (r1 >= NT) r1 = NT - 1;
            if (r2 >= NT) r2 = NT - 1;
            const float* q1 = g_qkv + (size_t)r1 * 384 + h * 32;
            const float* q2 = g_qkv + (size_t)r2 * 384 + h * 32;
#pragma unroll
            for (int ks = 0; ks < 2; ks++) {
#pragma unroll
                for (int p = 0; p < 2; p++) {     // k-octet within k16
                    int d0 = ks * 16 + p * 8 + fc;
                    float x1 = q1[d0] * scale, y1 = q1[d0 + 1] * scale;
                    float x2 = q2[d0] * scale, y2 = q2[d0 + 1] * scale;
                    bf16 hx1, lx1, hy1, ly1, hx2, lx2, hy2, ly2;
                    split_bf16(x1, hx1, lx1); split_bf16(y1, hy1, ly1);
                    split_bf16(x2, hx2, lx2); split_bf16(y2, hy2, ly2);
                    qh[ks][p * 2 + 0] = pack2(hx1, hy1);
                    qh[ks][p * 2 + 1] = pack2(hx2, hy2);
                    ql[ks][p * 2 + 0] = pack2(lx1, ly1);
                    ql[ks][p * 2 + 1] = pack2(lx2, ly2);
                }
            }
        }
        // reorder to mma a-frag: a0=(r,k0) a1=(r+8,k0) a2=(r,k8) a3=(r+8,k8)  -- already matches

        // ---- S = Q K^T ----
        for (int nt = 0; nt < tiles; nt++) {
            float sacc[2][4];
#pragma unroll
            for (int i = 0; i < 2; i++)
#pragma unroll
                for (int q = 0; q < 4; q++) sacc[i][q] = 0.f;
            uint32_t bh[2][2][2], bl[2][2][2];  // [kstep][n8][pair]
#pragma unroll
            for (int ks = 0; ks < 2; ks++) {
                uint32_t ad = (uint32_t)(nt * 16 * 80) + kb_off + ks * 32;
                uint32_t t4[4];
                ldm_x4(t4, aKh + ad);
                bh[ks][0][0] = t4[0]; bh[ks][0][1] = t4[1];
                bh[ks][1][0] = t4[2]; bh[ks][1][1] = t4[3];
                ldm_x4(t4, aKl + ad);
                bl[ks][0][0] = t4[0]; bl[ks][0][1] = t4[1];
                bl[ks][1][0] = t4[2]; bl[ks][1][1] = t4[3];
            }
#pragma unroll
            for (int n8 = 0; n8 < 2; n8++)
#pragma unroll
                for (int ks = 0; ks < 2; ks++) {
                    mma_bf16(sacc[n8], qh[ks], bh[ks][n8][0], bh[ks][n8][1]);
                    mma_bf16(sacc[n8], qh[ks], bl[ks][n8][0], bl[ks][n8][1]);
                    mma_bf16(sacc[n8], ql[ks], bh[ks][n8][0], bh[ks][n8][1]);
                }
#pragma unroll
            for (int n8 = 0; n8 < 2; n8++) {
                int col = nt * 16 + n8 * 8 + fc;
                Sbuf[fr * 257 + col] = sacc[n8][0];
                Sbuf[fr * 257 + col + 1] = sacc[n8][1];
                Sbuf[(fr + 8) * 257 + col] = sacc[n8][2];
                Sbuf[(fr + 8) * 257 + col + 1] = sacc[n8][3];
            }
        }
        __syncwarp();

        // ---- softmax (2 lanes per row, cols strided by 2) ----
        {
            int sr = lane & 15, sc = lane >> 4;
            float mx = -1e30f;
            for (int c2 = sc; c2 < cnt; c2 += 2)
                mx = fmaxf(mx, Sbuf[sr * 257 + c2]);
            mx = fmaxf(mx, __shfl_xor_sync(0xffffffffu, mx, 16));
            float sum = 0.f;
            for (int c2 = sc; c2 < ncols; c2 += 2) {
                float p = (c2 < cnt) ? __expf(Sbuf[sr * 257 + c2] - mx) : 0.f;
                sum += p;
                bf16 ph, pl;
                split_bf16(p, ph, pl);
                Ph[sr * 264 + c2] = ph;
                Pl[sr * 264 + c2] = pl;
            }
            sum += __shfl_xor_sync(0xffffffffu, sum, 16);
            if (lane < 16) Sbuf[sr * 257 + 256] = 1.f / sum;
        }
        __syncwarp();

        // ---- O = P V ----
        float o[4][4];
#pragma unroll
        for (int i = 0; i < 4; i++)
#pragma unroll
            for (int q = 0; q < 4; q++) o[i][q] = 0.f;

        for (int kt = 0; kt < tiles; kt++) {
            uint32_t pa[4], pla[4];
            uint32_t pad = (uint32_t)((lane & 15) * 528 + kt * 32 + ((lane >> 4) << 4));
            ldm_x4(pa, aPh + pad);
            ldm_x4(pla, aPl + pad);
            uint32_t vh[4][2], vl[4][2];  // [n8][pair]
#pragma unroll
            for (int cc = 0; cc < 2; cc++) {   // dim chunks 0-15, 16-31
                uint32_t ad = (uint32_t)(kt * 16 * 80) + vt_off + cc * 32;
                uint32_t t4[4];
                ldm_x4_t(t4, aVh + ad);
                vh[cc * 2][0] = t4[0]; vh[cc * 2][1] = t4[1];
                vh[cc * 2 + 1][0] = t4[2]; vh[cc * 2 + 1][1] = t4[3];
                ldm_x4_t(t4, aVl + ad);
                vl[cc * 2][0] = t4[0]; vl[cc * 2][1] = t4[1];
                vl[cc * 2 + 1][0] = t4[2]; vl[cc * 2 + 1][1] = t4[3];
            }
#pragma unroll
            for (int nn = 0; nn < 4; nn++) {
                mma_bf16(o[nn], pa, vh[nn][0], vh[nn][1]);
                mma_bf16(o[nn], pa, vl[nn][0], vl[nn][1]);
                mma_bf16(o[nn], pla, vh[nn][0], vh[nn][1]);
            }
        }

        // ---- epilogue ----
        float i1 = Sbuf[fr * 257 + 256];
        float i2 = Sbuf[(fr + 8) * 257 + 256];
        int r1 = m0t + fr, r2 = r1 + 8;
#pragma unroll
        for (int nn = 0; nn < 4; nn++) {
            int col = h * 32 + nn * 8 + fc;
            if (r1 < cnt) {
                float v0 = o[nn][0] * i1, v1 = o[nn][1] * i1;
                bf16 h0, l0, h1, l1;
                split_bf16(v0, h0, l0); split_bf16(v1, h1, l1);
                size_t off = (size_t)(start + r1) * DD + col;
                *(uint32_t*)(g_ah + off) = pack2(h0, h1);
                *(uint32_t*)(g_al + off) = pack2(l0, l1);
            }
            if (r2 < cnt) {
                float v0 = o[nn][2] * i2, v1 = o[nn][3] * i2;
                bf16 h0, l0, h1, l1;
                split_bf16(v0, h0, l0); split_bf16(v1, h1, l1);
                size_t off = (size_t)(start + r2) * DD + col;
                *(uint32_t*)(g_ah + off) = pack2(h0, h1);
                *(uint32_t*)(g_al + off) = pack2(l0, l1);
            }
        }
        __syncwarp();
    }
}

// ---------------- final projection ----------------
__global__ void out_kernel(const float* __restrict__ w_out, const float* __restrict__ b_out,
                           float* __restrict__ out) {
    int row = blockIdx.x;
    int t = threadIdx.x;
    float x = __bfloat162float(g_yh[(size_t)row * DD + t]) +
              __bfloat162float(g_yl[(size_t)row * DD + t]);
    float p0 = x * w_out[t * 4 + 0];
    float p1 = x * w_out[t * 4 + 1];
    float p2 = x * w_out[t * 4 + 2];
    float p3 = x * w_out[t * 4 + 3];
#pragma unroll
    for (int o = 16; o; o >>= 1) {
        p0 += __shfl_xor_sync(0xffffffffu, p0, o);
        p1 += __shfl_xor_sync(0xffffffffu, p1, o);
        p2 += __shfl_xor_sync(0xffffffffu, p2, o);
        p3 += __shfl_xor_sync(0xffffffffu, p3, o);
    }
    __shared__ float s4[4][4];
    int w = t >> 5, l = t & 31;
    if (l == 0) { s4[w][0] = p0; s4[w][1] = p1; s4[w][2] = p2; s4[w][3] = p3; }
    __syncthreads();
    if (t < 4) {
        float v = s4[0][t] + s4[1][t] + s4[2][t] + s4[3][t] + b_out[t];
        if (t == 3) v = 1.f / (1.f + __expf(-v));
        out[row * 4 + t] = v;
    }
}

// ---------------- launcher ----------------
extern "C" void kernel_launch(void* const* d_in, const int* in_sizes, int n_in,
                              void* d_out, int out_size) {
    const float* inputs_scalar = (const float*)d_in[0];
    const float* inputs_v      = (const float*)d_in[1];
    const int*   batch_idx     = (const int*)  d_in[2];
    const float* bn_gamma      = (const float*)d_in[3];
    const float* bn_beta       = (const float*)d_in[4];
    const float* w_in          = (const float*)d_in[5];
    const float* b_in          = (const float*)d_in[6];
    const float* ln1_g         = (const float*)d_in[7];
    const float* ln1_b         = (const float*)d_in[8];
    const float* w_qkv         = (const float*)d_in[9];
    const float* b_qkv         = (const float*)d_in[10];
    const float* w_o           = (const float*)d_in[11];
    const float* b_o           = (const float*)d_in[12];
    const float* ln2_g         = (const float*)d_in[13];
    const float* ln2_b         = (const float*)d_in[14];
    const float* w_m1          = (const float*)d_in[15];
    const float* b_m1          = (const float*)d_in[16];
    const float* w_m2          = (const float*)d_in[17];
    const float* b_m2          = (const float*)d_in[18];
    const float* lnf_g         = (const float*)d_in[19];
    const float* lnf_b         = (const float*)d_in[20];
    const float* w_out         = (const float*)d_in[21];
    const float* b_out         = (const float*)d_in[22];
    float* out = (float*)d_out;

    (void)in_sizes; (void)n_in; (void)out_size;

    cudaFuncSetAttribute(attn_tc, cudaFuncAttributeMaxDynamicSharedMemorySize, AT_SMEM);
    cudaFuncSetAttribute(gemm_mma<0>, cudaFuncAttributeMaxDynamicSharedMemorySize, GEMM_SMEM);
    cudaFuncSetAttribute(gemm_mma<1>, cudaFuncAttributeMaxDynamicSharedMemorySize, GEMM_SMEM);
    cudaFuncSetAttribute(gemm_mma<2>, cudaFuncAttributeMaxDynamicSharedMemorySize, GEMM_SMEM);

    float *px, *pq;
    bf16 *yh, *yl, *ah, *al, *mh, *ml;
    cudaGetSymbolAddress((void**)&px, g_x);
    cudaGetSymbolAddress((void**)&pq, g_qkv);
    cudaGetSymbolAddress((void**)&yh, g_yh);
    cudaGetSymbolAddress((void**)&yl, g_yl);
    cudaGetSymbolAddress((void**)&ah, g_ah);
    cudaGetSymbolAddress((void**)&al, g_al);
    cudaGetSymbolAddress((void**)&mh, g_mh);
    cudaGetSymbolAddress((void**)&ml, g_ml);
    bf16 *wqh, *wql, *woh, *wol, *w1h, *w1l, *w2h, *w2l;
    cudaGetSymbolAddress((void**)&wqh, g_wq_hi);
    cudaGetSymbolAddress((void**)&wql, g_wq_lo);
    cudaGetSymbolAddress((void**)&woh, g_wo_hi);
    cudaGetSymbolAddress((void**)&wol, g_wo_lo);
    cudaGetSymbolAddress((void**)&w1h, g_wm1_hi);
    cudaGetSymbolAddress((void**)&w1l, g_wm1_lo);
    cudaGetSymbolAddress((void**)&w2h, g_wm2_hi);
    cudaGetSymbolAddress((void**)&w2l, g_wm2_lo);

    wprep_kernel<<<(NBLK * 384 * 128 + 255) / 256, 256>>>(w_qkv, wqh, wql, 128, 384);
    wprep_kernel<<<(NBLK * 128 * 128 + 255) / 256, 256>>>(w_o,   woh, wol, 128, 128);
    wprep_kernel<<<(NBLK * 512 * 128 + 255) / 256, 256>>>(w_m1,  w1h, w1l, 128, 512);
    wprep_kernel<<<(NBLK * 128 * 512 + 255) / 256, 256>>>(w_m2,  w2h, w2l, 512, 128);

    bn_stats_kernel<<<16, 256>>>(inputs_scalar, inputs_v);
    seg_kernel<<<1, 256>>>(batch_idx);
    embed_kernel<<<NT, 128>>>(inputs_scalar, inputs_v, bn_gamma, bn_beta, w_in, b_in);

    for (int i = 0; i < NBLK; i++) {
        ln_kernel<<<NT / 8, 256>>>(ln1_g + i * DD, ln1_b + i * DD);
        gemm_mma<0><<<dim3(3, NT / 128), 256, GEMM_SMEM>>>(
            yh, yl, wqh + (size_t)i * 384 * 128, wql + (size_t)i * 384 * 128,
            b_qkv + i * 3 * DD, nullptr, pq, nullptr, nullptr, 128, 384);
        attn_tc<<<dim3(GN, HN), 128, AT_SMEM>>>();
        gemm_mma<1><<<dim3(1, NT / 128), 256, GEMM_SMEM>>>(
            ah, al, woh + (size_t)i * 128 * 128, wol + (size_t)i * 128 * 128,
            b_o + i * DD, px, px, nullptr, nullptr, 128, 128);
        ln_kernel<<<NT / 8, 256>>>(ln2_g + i * DD, ln2_b + i * DD);
        gemm_mma<2><<<dim3(4, NT / 128), 256, GEMM_SMEM>>>(
            yh, yl, w1h + (size_t)i * 512 * 128, w1l + (size_t)i * 512 * 128,
            b_m1 + i * 4 * DD, nullptr, nullptr, mh, ml, 128, 512);
        gemm_mma<1><<<dim3(1, NT / 128), 256, GEMM_SMEM>>>(
            mh, ml, w2h + (size_t)i * 128 * 512, w2l + (size_t)i * 128 * 512,
            b_m2 + i * DD, px, px, nullptr, nullptr, 512, 128);
    }

    ln_kernel<<<NT / 8, 256>>>(lnf_g, lnf_b);
    out_kernel<<<NT, 128>>>(w_out, b_out, out);
}

// round 5
// speedup vs baseline: 1.3821x; 1.3821x over previous
#include <cuda_runtime.h>
#include <cuda_bf16.h>
#include <cstdint>
#include <math.h>

#define NT   16384
#define GN   128
#define DD   128
#define HN   4
#define DHD  32
#define NBLK 10
#define MAXL 256
#define EPSV 1e-5f

typedef __nv_bfloat16 bf16;

// ---------------- scratch ----------------
__device__ float g_x  [NT * DD];          // residual stream (fp32)
__device__ bf16  g_qh [NT * 3 * DD];      // qkv hi/lo (bf16)
__device__ bf16  g_ql [NT * 3 * DD];
__device__ bf16  g_yh [NT * DD];          // LN output hi/lo
__device__ bf16  g_yl [NT * DD];
__device__ bf16  g_ah [NT * DD];          // attention output hi/lo
__device__ bf16  g_al [NT * DD];
__device__ bf16  g_mh [NT * 4 * DD];      // MLP hidden hi/lo
__device__ bf16  g_ml [NT * 4 * DD];
__device__ float g_bn_mean[16];
__device__ float g_bn_rstd[16];
__device__ int   g_seg[GN + 1];

// bf16 hi/lo weights, transposed to [N][K]
__device__ bf16 g_wq_hi [NBLK * 384 * 128];
__device__ bf16 g_wq_lo [NBLK * 384 * 128];
__device__ bf16 g_wo_hi [NBLK * 128 * 128];
__device__ bf16 g_wo_lo [NBLK * 128 * 128];
__device__ bf16 g_wm1_hi[NBLK * 512 * 128];
__device__ bf16 g_wm1_lo[NBLK * 512 * 128];
__device__ bf16 g_wm2_hi[NBLK * 128 * 512];
__device__ bf16 g_wm2_lo[NBLK * 128 * 512];

// ---------------- asm helpers ----------------
__device__ __forceinline__ uint32_t smem_u32(const void* p) {
    uint32_t a;
    asm("{ .reg .u64 t; cvta.to.shared.u64 t, %1; cvt.u32.u64 %0, t; }" : "=r"(a) : "l"(p));
    return a;
}
__device__ __forceinline__ void cp16(uint32_t dst, const void* src) {
    asm volatile("cp.async.cg.shared.global [%0], [%1], 16;" :: "r"(dst), "l"(src));
}
#define CP_COMMIT() asm volatile("cp.async.commit_group;" ::: "memory")
#define CP_WAIT(n)  asm volatile("cp.async.wait_group %0;" :: "n"(n) : "memory")

__device__ __forceinline__ void ldm_x4(uint32_t r[4], uint32_t a) {
    asm volatile("ldmatrix.sync.aligned.m8n8.x4.shared.b16 {%0,%1,%2,%3}, [%4];"
                 : "=r"(r[0]), "=r"(r[1]), "=r"(r[2]), "=r"(r[3]) : "r"(a));
}
__device__ __forceinline__ void ldm_x4_t(uint32_t r[4], uint32_t a) {
    asm volatile("ldmatrix.sync.aligned.m8n8.x4.trans.shared.b16 {%0,%1,%2,%3}, [%4];"
                 : "=r"(r[0]), "=r"(r[1]), "=r"(r[2]), "=r"(r[3]) : "r"(a));
}
__device__ __forceinline__ void mma_bf16(float c[4], const uint32_t a[4],
                                         uint32_t b0, uint32_t b1) {
    asm volatile(
        "mma.sync.aligned.m16n8k16.row.col.f32.bf16.bf16.f32 "
        "{%0,%1,%2,%3}, {%4,%5,%6,%7}, {%8,%9}, {%0,%1,%2,%3};"
        : "+f"(c[0]), "+f"(c[1]), "+f"(c[2]), "+f"(c[3])
        : "r"(a[0]), "r"(a[1]), "r"(a[2]), "r"(a[3]), "r"(b0), "r"(b1));
}

__device__ __forceinline__ void split_bf16(float v, bf16& hi, bf16& lo) {
    hi = __float2bfloat16(v);
    lo = __float2bfloat16(v - __bfloat162float(hi));
}
__device__ __forceinline__ uint32_t pack2(bf16 a, bf16 b) {
    __nv_bfloat162 t = {a, b};
    return *(uint32_t*)&t;
}
__device__ __forceinline__ float fast_gelu(float u) {
    float z = 0.7978845608028654f * (u + 0.044715f * u * u * u);
    float t = 1.f - 2.f / (__expf(2.f * z) + 1.f);
    return 0.5f * u * (1.f + t);
}

// ---------------- BN batch stats ----------------
__global__ void bn_stats_kernel(const float* __restrict__ s, const float* __restrict__ v) {
    int f = blockIdx.x, t = threadIdx.x;
    float sum = 0.f, sq = 0.f;
    for (int i = t; i < NT; i += 256) {
        float x = (f < 13) ? s[i * 13 + f] : v[i * 3 + (f - 13)];
        sum += x; sq += x * x;
    }
    __shared__ float rs[256], rq[256];
    rs[t] = sum; rq[t] = sq;
    __syncthreads();
    for (int st = 128; st > 0; st >>= 1) {
        if (t < st) { rs[t] += rs[t + st]; rq[t] += rq[t + st]; }
        __syncthreads();
    }
    if (t == 0) {
        float m = rs[0] * (1.f / NT);
        float var = rq[0] * (1.f / NT) - m * m;
        g_bn_mean[f] = m;
        g_bn_rstd[f] = rsqrtf(var + EPSV);
    }
}

// ---------------- segment offsets ----------------
__global__ void seg_kernel(const int* __restrict__ bidx) {
    int g = threadIdx.x;
    if (g > GN) return;
    int lo = 0, hi = NT;
    while (lo < hi) {
        int mid = (lo + hi) >> 1;
        if (bidx[mid] < g) lo = mid + 1; else hi = mid;
    }
    g_seg[g] = lo;
}

// ---------------- BN + embed ----------------
__global__ void embed_kernel(const float* __restrict__ s, const float* __restrict__ v,
                             const float* __restrict__ gamma, const float* __restrict__ beta,
                             const float* __restrict__ w_in, const float* __restrict__ b_in) {
    int row = blockIdx.x, t = threadIdx.x;
    __shared__ float xn[16];
    if (t < 16) {
        float x = (t < 13) ? s[row * 13 + t] : v[row * 3 + (t - 13)];
        xn[t] = (x - g_bn_mean[t]) * g_bn_rstd[t] * gamma[t] + beta[t];
    }
    __syncthreads();
    float acc = b_in[t];
#pragma unroll
    for (int k = 0; k < 16; k++) acc += xn[k] * w_in[k * DD + t];
    g_x[row * DD + t] = acc;
}

// ---------------- LayerNorm: warp per row -> hi/lo bf16 ----------------
__global__ __launch_bounds__(256)
void ln_kernel(const float* __restrict__ gam, const float* __restrict__ bet) {
    int w = threadIdx.x >> 5, lane = threadIdx.x & 31;
    int row = blockIdx.x * 8 + w;
    const float* xp = g_x + (size_t)row * DD;
    float4 xv = *(const float4*)(xp + lane * 4);
    float s = xv.x + xv.y + xv.z + xv.w;
    float sq = xv.x * xv.x + xv.y * xv.y + xv.z * xv.z + xv.w * xv.w;
#pragma unroll
    for (int o = 16; o; o >>= 1) {
        s  += __shfl_xor_sync(0xffffffffu, s,  o);
        sq += __shfl_xor_sync(0xffffffffu, sq, o);
    }
    float m = s * (1.f / DD);
    float var = sq * (1.f / DD) - m * m;
    float r = rsqrtf(var + EPSV);
    float4 gv = *(const float4*)(gam + lane * 4);
    float4 bv = *(const float4*)(bet + lane * 4);
    float o0 = (xv.x - m) * r * gv.x + bv.x;
    float o1 = (xv.y - m) * r * gv.y + bv.y;
    float o2 = (xv.z - m) * r * gv.z + bv.z;
    float o3 = (xv.w - m) * r * gv.w + bv.w;
    bf16 h[4], l[4];
    split_bf16(o0, h[0], l[0]); split_bf16(o1, h[1], l[1]);
    split_bf16(o2, h[2], l[2]); split_bf16(o3, h[3], l[3]);
    *(uint2*)(g_yh + (size_t)row * DD + lane * 4) = *(uint2*)h;
    *(uint2*)(g_yl + (size_t)row * DD + lane * 4) = *(uint2*)l;
}

// ---------------- weight prep ----------------
__global__ void wprep_kernel(const float* __restrict__ w, bf16* __restrict__ whi,
                             bf16* __restrict__ wlo, int K, int N) {
    int idx = blockIdx.x * 256 + threadIdx.x;
    int total = NBLK * N * K;
    if (idx >= total) return;
    int k = idx % K;
    int n = (idx / K) % N;
    int b = idx / (K * N);
    float x = w[(size_t)b * K * N + (size_t)k * N + n];
    bf16 hi, lo;
    split_bf16(x, hi, lo);
    whi[idx] = hi;
    wlo[idx] = lo;
}

// ---------------- mma.sync GEMM, 4-stage cp.async pipeline ----------------
// CTA 128x128, BK=16, 8 warps (32x64 each).
// FUSE: 0 bias->fp32, 1 bias+residual->fp32, 2 bias+gelu->hi/lo, 3 bias->hi/lo
#define STG 24576
#define OFF_AH 0
#define OFF_AL 6144
#define OFF_BH 12288
#define OFF_BL 18432
#define GEMM_SMEM (4 * STG)

template <int FUSE>
__global__ __launch_bounds__(256)
void gemm_mma(const bf16* __restrict__ Ahi, const bf16* __restrict__ Alo,
              const bf16* __restrict__ Bhi, const bf16* __restrict__ Blo,
              const float* __restrict__ bias, const float* __restrict__ R,
              float* __restrict__ C, bf16* __restrict__ Chi, bf16* __restrict__ Clo,
              int K, int Nc) {
    extern __shared__ char smem[];
    uint32_t sb = smem_u32(smem);
    int tid = threadIdx.x, lane = tid & 31, wid = tid >> 5;
    int wm = wid & 3, wn = wid >> 2;
    int m0 = blockIdx.y * 128, n0 = blockIdx.x * 128;

    int ldrow = tid >> 1, ldhalf = tid & 1;
    const bf16* pAh = Ahi + (size_t)(m0 + ldrow) * K + ldhalf * 8;
    const bf16* pAl = Alo + (size_t)(m0 + ldrow) * K + ldhalf * 8;
    const bf16* pBh = Bhi + (size_t)(n0 + ldrow) * K + ldhalf * 8;
    const bf16* pBl = Blo + (size_t)(n0 + ldrow) * K + ldhalf * 8;
    uint32_t dstb = sb + ldrow * 48 + ldhalf * 16;

    float acc[2][8][4];
#pragma unroll
    for (int i = 0; i < 2; i++)
#pragma unroll
        for (int j = 0; j < 8; j++)
#pragma unroll
            for (int q = 0; q < 4; q++) acc[i][j][q] = 0.f;

    int nsteps = K >> 4;

    // prologue: stages 0,1
#pragma unroll
    for (int s = 0; s < 2; s++) {
        if (s < nsteps) {
            uint32_t d = dstb + s * STG;
            int k0 = s << 4;
            cp16(d + OFF_AH, pAh + k0);
            cp16(d + OFF_AL, pAl + k0);
            cp16(d + OFF_BH, pBh + k0);
            cp16(d + OFF_BL, pBl + k0);
        }
        CP_COMMIT();
    }

    uint32_t a_off = (uint32_t)((wm * 32 + (lane & 15)) * 48 + (lane >> 4) * 16);
    uint32_t b_row = (uint32_t)(wn * 64 + (lane & 7) + ((lane >> 4) << 3));
    uint32_t b_off = b_row * 48 + (((lane >> 3) & 1) << 4);

    for (int c = 0; c < nsteps; c++) {
        if (c + 2 < nsteps) {
            int k0 = (c + 2) << 4;
            uint32_t d = dstb + ((c + 2) & 3) * STG;
            cp16(d + OFF_AH, pAh + k0);
            cp16(d + OFF_AL, pAl + k0);
            cp16(d + OFF_BH, pBh + k0);
            cp16(d + OFF_BL, pBl + k0);
        }
        CP_COMMIT();
        CP_WAIT(2);
        __syncthreads();

        uint32_t sA = sb + (c & 3) * STG;
        uint32_t sB = sA + OFF_BH;

        uint32_t ah[2][4], al[2][4];
#pragma unroll
        for (int mt = 0; mt < 2; mt++) {
            uint32_t addr = sA + a_off + mt * 16 * 48;
            ldm_x4(ah[mt], addr + OFF_AH);
            ldm_x4(al[mt], addr + OFF_AL);
        }
        uint32_t bh[8][2], bl[8][2];
#pragma unroll
        for (int g4 = 0; g4 < 4; g4++) {
            uint32_t addr = sB + b_off + g4 * 16 * 48;
            uint32_t t4[4];
            ldm_x4(t4, addr);
            bh[g4 * 2][0] = t4[0]; bh[g4 * 2][1] = t4[1];
            bh[g4 * 2 + 1][0] = t4[2]; bh[g4 * 2 + 1][1] = t4[3];
            ldm_x4(t4, addr + (OFF_BL - OFF_BH));
            bl[g4 * 2][0] = t4[0]; bl[g4 * 2][1] = t4[1];
            bl[g4 * 2 + 1][0] = t4[2]; bl[g4 * 2 + 1][1] = t4[3];
        }
#pragma unroll
        for (int mt = 0; mt < 2; mt++)
#pragma unroll
            for (int nt = 0; nt < 8; nt++) {
                mma_bf16(acc[mt][nt], ah[mt], bh[nt][0], bh[nt][1]);
                mma_bf16(acc[mt][nt], ah[mt], bl[nt][0], bl[nt][1]);
                mma_bf16(acc[mt][nt], al[mt], bh[nt][0], bh[nt][1]);
            }
    }

    int lane4 = lane >> 2, lanem = (lane & 3) * 2;
#pragma unroll
    for (int mt = 0; mt < 2; mt++) {
#pragma unroll
        for (int nt = 0; nt < 8; nt++) {
            int col = n0 + wn * 64 + nt * 8 + lanem;
            int r0 = m0 + wm * 32 + mt * 16 + lane4;
            float b0 = bias[col], b1 = bias[col + 1];
#pragma unroll
            for (int half = 0; half < 2; half++) {
                int r = r0 + half * 8;
                float v0 = acc[mt][nt][half * 2 + 0] + b0;
                float v1 = acc[mt][nt][half * 2 + 1] + b1;
                size_t o = (size_t)r * Nc + col;
                if (FUSE == 1) {
                    float2 rr = *(const float2*)(R + o);
                    v0 += rr.x; v1 += rr.y;
                }
                if (FUSE == 2 || FUSE == 3) {
                    if (FUSE == 2) {
                        v0 = fast_gelu(v0);
                        v1 = fast_gelu(v1);
                    }
                    bf16 h0, l0, h1, l1;
                    split_bf16(v0, h0, l0);
                    split_bf16(v1, h1, l1);
                    *(uint32_t*)(Chi + o) = pack2(h0, h1);
                    *(uint32_t*)(Clo + o) = pack2(l0, l1);
                } else {
                    float2 ov = {v0, v1};
                    *(float2*)(C + o) = ov;
                }
            }
        }
    }
}

// ---------------- flash segment attention: register-resident softmax ----------------
// CTA per (graph, head), 8 warps. Warp owns m16 query tiles (strided by 8).
// smem: K/V hi/lo only, 80B rows, staged via cp.async. S frags -> P a-frags directly.
#define AT_ROWB 80
#define AT_ARR  (MAXL * AT_ROWB)          // 20480 per array
#define AT_SMEM (4 * AT_ARR)              // 81920

__global__ __launch_bounds__(256)
void attn_flash() {
    extern __shared__ char sm[];
    bf16* sKh = (bf16*)sm;
    bf16* sKl = (bf16*)(sm + AT_ARR);
    bf16* sVh = (bf16*)(sm + 2 * AT_ARR);
    bf16* sVl = (bf16*)(sm + 3 * AT_ARR);

    int g = blockIdx.x, h = blockIdx.y;
    int start = g_seg[g];
    int cnt = g_seg[g + 1] - start;
    if (cnt <= 0) return;
    if (cnt > MAXL) cnt = MAXL;
    int tid = threadIdx.x, lane = tid & 31, wid = tid >> 5;
    int tiles = (cnt + 15) >> 4;
    int ncols = tiles << 4;

    uint32_t aKh = smem_u32(sKh), aKl = smem_u32(sKl);
    uint32_t aVh = smem_u32(sVh), aVl = smem_u32(sVl);

    // zero pad rows [cnt, ncols)
    {
        uint4 z = {0, 0, 0, 0};
        int npad = (ncols - cnt) * 4;
        for (int idx = tid; idx < npad; idx += 256) {
            int j = cnt + (idx >> 2), c = idx & 3;
            int o = j * AT_ROWB + c * 16;
            *(uint4*)((char*)sKh + o) = z;
            *(uint4*)((char*)sKl + o) = z;
            *(uint4*)((char*)sVh + o) = z;
            *(uint4*)((char*)sVl + o) = z;
        }
    }
    // stage K/V hi/lo via cp.async (16B chunks)
    for (int idx = tid; idx < cnt * 4; idx += 256) {
        int j = idx >> 2, c = idx & 3;
        size_t base = (size_t)(start + j) * 384 + h * 32 + c * 8;
        uint32_t d = (uint32_t)(j * AT_ROWB + c * 16);
        cp16(aKh + d, g_qh + base + 128);
        cp16(aKl + d, g_ql + base + 128);
        cp16(aVh + d, g_qh + base + 256);
        cp16(aVl + d, g_ql + base + 256);
    }
    CP_COMMIT();
    CP_WAIT(0);
    __syncthreads();

    const float scale = 0.17677669529663687f;  // 1/sqrt(32)
    int fr = lane >> 2, fc = (lane & 3) * 2;
    uint32_t kb_row = (uint32_t)((lane & 7) + ((lane >> 4) << 3));
    uint32_t kb_off = kb_row * AT_ROWB + (((lane >> 3) & 1) << 4);
    uint32_t vt_off = (uint32_t)((lane & 15) * AT_ROWB + ((lane >> 4) << 4));

    for (int mt = wid; mt < tiles; mt += 8) {
        // Q frags hi/lo: direct packed loads (rows clamped)
        uint32_t qh[2][4], ql[2][4];
        {
            int r1 = start + (mt << 4) + fr, r2 = r1 + 8;
            if (r1 >= NT) r1 = NT - 1;
            if (r2 >= NT) r2 = NT - 1;
            const bf16* q1h = g_qh + (size_t)r1 * 384 + h * 32;
            const bf16* q2h = g_qh + (size_t)r2 * 384 + h * 32;
            const bf16* q1l = g_ql + (size_t)r1 * 384 + h * 32;
            const bf16* q2l = g_ql + (size_t)r2 * 384 + h * 32;
#pragma unroll
            for (int ks = 0; ks < 2; ks++) {
                int d0 = ks * 16 + fc, d8 = d0 + 8;
                qh[ks][0] = *(const uint32_t*)(q1h + d0);
                qh[ks][1] = *(const uint32_t*)(q2h + d0);
                qh[ks][2] = *(const uint32_t*)(q1h + d8);
                qh[ks][3] = *(const uint32_t*)(q2h + d8);
                ql[ks][0] = *(const uint32_t*)(q1l + d0);
                ql[ks][1] = *(const uint32_t*)(q2l + d0);
                ql[ks][2] = *(const uint32_t*)(q1l + d8);
                ql[ks][3] = *(const uint32_t*)(q2l + d8);
            }
        }

        float o[4][4];
#pragma unroll
        for (int i = 0; i < 4; i++)
#pragma unroll
            for (int q = 0; q < 4; q++) o[i][q] = 0.f;
        float m_r = -1e30f, m_r8 = -1e30f;
        float l_r = 0.f, l_r8 = 0.f;

        for (int kt = 0; kt < tiles; kt++) {
            // S = Q K^T (compensated)
            float sacc[2][4];
#pragma unroll
            for (int i = 0; i < 2; i++)
#pragma unroll
                for (int q = 0; q < 4; q++) sacc[i][q] = 0.f;
            {
                uint32_t bhf[2][2][2], blf[2][2][2];
#pragma unroll
                for (int ks = 0; ks < 2; ks++) {
                    uint32_t ad = (uint32_t)(kt * 16 * AT_ROWB) + kb_off + ks * 32;
                    uint32_t t4[4];
                    ldm_x4(t4, aKh + ad);
                    bhf[ks][0][0] = t4[0]; bhf[ks][0][1] = t4[1];
                    bhf[ks][1][0] = t4[2]; bhf[ks][1][1] = t4[3];
                    ldm_x4(t4, aKl + ad);
                    blf[ks][0][0] = t4[0]; blf[ks][0][1] = t4[1];
                    blf[ks][1][0] = t4[2]; blf[ks][1][1] = t4[3];
                }
#pragma unroll
                for (int n8 = 0; n8 < 2; n8++)
#pragma unroll
                    for (int ks = 0; ks < 2; ks++) {
                        mma_bf16(sacc[n8], qh[ks], bhf[ks][n8][0], bhf[ks][n8][1]);
                        mma_bf16(sacc[n8], qh[ks], blf[ks][n8][0], blf[ks][n8][1]);
                        mma_bf16(sacc[n8], ql[ks], bhf[ks][n8][0], bhf[ks][n8][1]);
                    }
            }
            // scale + mask
            float sv[2][4];
#pragma unroll
            for (int n8 = 0; n8 < 2; n8++)
#pragma unroll
                for (int q = 0; q < 4; q++) {
                    int col = kt * 16 + n8 * 8 + fc + (q & 1);
                    sv[n8][q] = (col < cnt) ? sacc[n8][q] * scale : -1e30f;
                }
            // tile row max
            float tm_r  = fmaxf(fmaxf(sv[0][0], sv[0][1]), fmaxf(sv[1][0], sv[1][1]));
            float tm_r8 = fmaxf(fmaxf(sv[0][2], sv[0][3]), fmaxf(sv[1][2], sv[1][3]));
#pragma unroll
            for (int oX = 1; oX <= 2; oX <<= 1) {
                tm_r  = fmaxf(tm_r,  __shfl_xor_sync(0xffffffffu, tm_r,  oX));
                tm_r8 = fmaxf(tm_r8, __shfl_xor_sync(0xffffffffu, tm_r8, oX));
            }
            float Mn_r = fmaxf(m_r, tm_r), Mn_r8 = fmaxf(m_r8, tm_r8);
            float cr = __expf(m_r - Mn_r), cr8 = __expf(m_r8 - Mn_r8);
            m_r = Mn_r; m_r8 = Mn_r8;
            // p = exp(s - M)
            float p[2][4];
#pragma unroll
            for (int n8 = 0; n8 < 2; n8++) {
                p[n8][0] = __expf(sv[n8][0] - Mn_r);
                p[n8][1] = __expf(sv[n8][1] - Mn_r);
                p[n8][2] = __expf(sv[n8][2] - Mn_r8);
                p[n8][3] = __expf(sv[n8][3] - Mn_r8);
            }
            l_r  = l_r  * cr  + p[0][0] + p[0][1] + p[1][0] + p[1][1];
            l_r8 = l_r8 * cr8 + p[0][2] + p[0][3] + p[1][2] + p[1][3];
            // rescale O
#pragma unroll
            for (int nn = 0; nn < 4; nn++) {
                o[nn][0] *= cr;  o[nn][1] *= cr;
                o[nn][2] *= cr8; o[nn][3] *= cr8;
            }
            // P frags (S C-layout == P A-layout)
            uint32_t pa[4], pl[4];
            {
                bf16 h0, l0, h1, l1;
                split_bf16(p[0][0], h0, l0); split_bf16(p[0][1], h1, l1);
                pa[0] = pack2(h0, h1); pl[0] = pack2(l0, l1);
                split_bf16(p[0][2], h0, l0); split_bf16(p[0][3], h1, l1);
                pa[1] = pack2(h0, h1); pl[1] = pack2(l0, l1);
                split_bf16(p[1][0], h0, l0); split_bf16(p[1][1], h1, l1);
                pa[2] = pack2(h0, h1); pl[2] = pack2(l0, l1);
                split_bf16(p[1][2], h0, l0); split_bf16(p[1][3], h1, l1);
                pa[3] = pack2(h0, h1); pl[3] = pack2(l0, l1);
            }
            // V frags (trans) + O accumulation
            uint32_t vhf[4][2], vlf[4][2];
#pragma unroll
            for (int cc = 0; cc < 2; cc++) {
                uint32_t ad = (uint32_t)(kt * 16 * AT_ROWB) + vt_off + cc * 32;
                uint32_t t4[4];
                ldm_x4_t(t4, aVh + ad);
                vhf[cc * 2][0] = t4[0]; vhf[cc * 2][1] = t4[1];
                vhf[cc * 2 + 1][0] = t4[2]; vhf[cc * 2 + 1][1] = t4[3];
                ldm_x4_t(t4, aVl + ad);
                vlf[cc * 2][0] = t4[0]; vlf[cc * 2][1] = t4[1];
                vlf[cc * 2 + 1][0] = t4[2]; vlf[cc * 2 + 1][1] = t4[3];
            }
#pragma unroll
            for (int nn = 0; nn < 4; nn++) {
                mma_bf16(o[nn], pa, vhf[nn][0], vhf[nn][1]);
                mma_bf16(o[nn], pa, vlf[nn][0], vlf[nn][1]);
                mma_bf16(o[nn], pl, vhf[nn][0], vhf[nn][1]);
            }
        }

        // final row-sum reduce + write
#pragma unroll
        for (int oX = 1; oX <= 2; oX <<= 1) {
            l_r  += __shfl_xor_sync(0xffffffffu, l_r,  oX);
            l_r8 += __shfl_xor_sync(0xffffffffu, l_r8, oX);
        }
        float i1 = 1.f / l_r, i2 = 1.f / l_r8;
        int lr1 = (mt << 4) + fr, lr2 = lr1 + 8;
#pragma unroll
        for (int nn = 0; nn < 4; nn++) {
            int col = h * 32 + nn * 8 + fc;
            if (lr1 < cnt) {
                float v0 = o[nn][0] * i1, v1 = o[nn][1] * i1;
                bf16 h0, l0, h1, l1;
                split_bf16(v0, h0, l0); split_bf16(v1, h1, l1);
                size_t off = (size_t)(start + lr1) * DD + col;
                *(uint32_t*)(g_ah + off) = pack2(h0, h1);
                *(uint32_t*)(g_al + off) = pack2(l0, l1);
            }
            if (lr2 < cnt) {
                float v0 = o[nn][2] * i2, v1 = o[nn][3] * i2;
                bf16 h0, l0, h1, l1;
                split_bf16(v0, h0, l0); split_bf16(v1, h1, l1);
                size_t off = (size_t)(start + lr2) * DD + col;
                *(uint32_t*)(g_ah + off) = pack2(h0, h1);
                *(uint32_t*)(g_al + off) = pack2(l0, l1);
            }
        }
    }
}

// ---------------- final projection ----------------
__global__ void out_kernel(const float* __restrict__ w_out, const float* __restrict__ b_out,
                           float* __restrict__ out) {
    int row = blockIdx.x;
    int t = threadIdx.x;
    float x = __bfloat162float(g_yh[(size_t)row * DD + t]) +
              __bfloat162float(g_yl[(size_t)row * DD + t]);
    float p0 = x * w_out[t * 4 + 0];
    float p1 = x * w_out[t * 4 + 1];
    float p2 = x * w_out[t * 4 + 2];
    float p3 = x * w_out[t * 4 + 3];
#pragma unroll
    for (int o = 16; o; o >>= 1) {
        p0 += __shfl_xor_sync(0xffffffffu, p0, o);
        p1 += __shfl_xor_sync(0xffffffffu, p1, o);
        p2 += __shfl_xor_sync(0xffffffffu, p2, o);
        p3 += __shfl_xor_sync(0xffffffffu, p3, o);
    }
    __shared__ float s4[4][4];
    int w = t >> 5, l = t & 31;
    if (l == 0) { s4[w][0] = p0; s4[w][1] = p1; s4[w][2] = p2; s4[w][3] = p3; }
    __syncthreads();
    if (t < 4) {
        float v = s4[0][t] + s4[1][t] + s4[2][t] + s4[3][t] + b_out[t];
        if (t == 3) v = 1.f / (1.f + __expf(-v));
        out[row * 4 + t] = v;
    }
}

// ---------------- launcher ----------------
extern "C" void kernel_launch(void* const* d_in, const int* in_sizes, int n_in,
                              void* d_out, int out_size) {
    const float* inputs_scalar = (const float*)d_in[0];
    const float* inputs_v      = (const float*)d_in[1];
    const int*   batch_idx     = (const int*)  d_in[2];
    const float* bn_gamma      = (const float*)d_in[3];
    const float* bn_beta       = (const float*)d_in[4];
    const float* w_in          = (const float*)d_in[5];
    const float* b_in          = (const float*)d_in[6];
    const float* ln1_g         = (const float*)d_in[7];
    const float* ln1_b         = (const float*)d_in[8];
    const float* w_qkv         = (const float*)d_in[9];
    const float* b_qkv         = (const float*)d_in[10];
    const float* w_o           = (const float*)d_in[11];
    const float* b_o           = (const float*)d_in[12];
    const float* ln2_g         = (const float*)d_in[13];
    const float* ln2_b         = (const float*)d_in[14];
    const float* w_m1          = (const float*)d_in[15];
    const float* b_m1          = (const float*)d_in[16];
    const float* w_m2          = (const float*)d_in[17];
    const float* b_m2          = (const float*)d_in[18];
    const float* lnf_g         = (const float*)d_in[19];
    const float* lnf_b         = (const float*)d_in[20];
    const float* w_out         = (const float*)d_in[21];
    const float* b_out         = (const float*)d_in[22];
    float* out = (float*)d_out;

    (void)in_sizes; (void)n_in; (void)out_size;

    cudaFuncSetAttribute(attn_flash, cudaFuncAttributeMaxDynamicSharedMemorySize, AT_SMEM);
    cudaFuncSetAttribute(gemm_mma<0>, cudaFuncAttributeMaxDynamicSharedMemorySize, GEMM_SMEM);
    cudaFuncSetAttribute(gemm_mma<1>, cudaFuncAttributeMaxDynamicSharedMemorySize, GEMM_SMEM);
    cudaFuncSetAttribute(gemm_mma<2>, cudaFuncAttributeMaxDynamicSharedMemorySize, GEMM_SMEM);
    cudaFuncSetAttribute(gemm_mma<3>, cudaFuncAttributeMaxDynamicSharedMemorySize, GEMM_SMEM);

    float* px;
    bf16 *qh, *ql, *yh, *yl, *ah, *al, *mh, *ml;
    cudaGetSymbolAddress((void**)&px, g_x);
    cudaGetSymbolAddress((void**)&qh, g_qh);
    cudaGetSymbolAddress((void**)&ql, g_ql);
    cudaGetSymbolAddress((void**)&yh, g_yh);
    cudaGetSymbolAddress((void**)&yl, g_yl);
    cudaGetSymbolAddress((void**)&ah, g_ah);
    cudaGetSymbolAddress((void**)&al, g_al);
    cudaGetSymbolAddress((void**)&mh, g_mh);
    cudaGetSymbolAddress((void**)&ml, g_ml);
    bf16 *wqh, *wql, *woh, *wol, *w1h, *w1l, *w2h, *w2l;
    cudaGetSymbolAddress((void**)&wqh, g_wq_hi);
    cudaGetSymbolAddress((void**)&wql, g_wq_lo);
    cudaGetSymbolAddress((void**)&woh, g_wo_hi);
    cudaGetSymbolAddress((void**)&wol, g_wo_lo);
    cudaGetSymbolAddress((void**)&w1h, g_wm1_hi);
    cudaGetSymbolAddress((void**)&w1l, g_wm1_lo);
    cudaGetSymbolAddress((void**)&w2h, g_wm2_hi);
    cudaGetSymbolAddress((void**)&w2l, g_wm2_lo);

    wprep_kernel<<<(NBLK * 384 * 128 + 255) / 256, 256>>>(w_qkv, wqh, wql, 128, 384);
    wprep_kernel<<<(NBLK * 128 * 128 + 255) / 256, 256>>>(w_o,   woh, wol, 128, 128);
    wprep_kernel<<<(NBLK * 512 * 128 + 255) / 256, 256>>>(w_m1,  w1h, w1l, 128, 512);
    wprep_kernel<<<(NBLK * 128 * 512 + 255) / 256, 256>>>(w_m2,  w2h, w2l, 512, 128);

    bn_stats_kernel<<<16, 256>>>(inputs_scalar, inputs_v);
    seg_kernel<<<1, 256>>>(batch_idx);
    embed_kernel<<<NT, 128>>>(inputs_scalar, inputs_v, bn_gamma, bn_beta, w_in, b_in);

    for (int i = 0; i < NBLK; i++) {
        ln_kernel<<<NT / 8, 256>>>(ln1_g + i * DD, ln1_b + i * DD);
        gemm_mma<3><<<dim3(3, NT / 128), 256, GEMM_SMEM>>>(
            yh, yl, wqh + (size_t)i * 384 * 128, wql + (size_t)i * 384 * 128,
            b_qkv + i * 3 * DD, nullptr, nullptr, qh, ql, 128, 384);
        attn_flash<<<dim3(GN, HN), 256, AT_SMEM>>>();
        gemm_mma<1><<<dim3(1, NT / 128), 256, GEMM_SMEM>>>(
            ah, al, woh + (size_t)i * 128 * 128, wol + (size_t)i * 128 * 128,
            b_o + i * DD, px, px, nullptr, nullptr, 128, 128);
        ln_kernel<<<NT / 8, 256>>>(ln2_g + i * DD, ln2_b + i * DD);
        gemm_mma<2><<<dim3(4, NT / 128), 256, GEMM_SMEM>>>(
            yh, yl, w1h + (size_t)i * 512 * 128, w1l + (size_t)i * 512 * 128,
            b_m1 + i * 4 * DD, nullptr, nullptr, mh, ml, 128, 512);
        gemm_mma<1><<<dim3(1, NT / 128), 256, GEMM_SMEM>>>(
            mh, ml, w2h + (size_t)i * 128 * 512, w2l + (size_t)i * 128 * 512,
            b_m2 + i * DD, px, px, nullptr, nullptr, 512, 128);
    }

    ln_kernel<<<NT / 8, 256>>>(lnf_g, lnf_b);
    out_kernel<<<NT, 128>>>(w_out, b_out, out);
}

// round 6
// speedup vs baseline: 1.3913x; 1.0067x over previous
#include <cuda_runtime.h>
#include <cuda_bf16.h>
#include <cstdint>
#include <math.h>

#define NT   16384
#define GN   128
#define DD   128
#define HN   4
#define DHD  32
#define NBLK 10
#define MAXL 256
#define EPSV 1e-5f

typedef __nv_bfloat16 bf16;

// ---------------- scratch ----------------
__device__ float g_x  [NT * DD];          // residual stream (fp32)
__device__ bf16  g_qh [NT * 3 * DD];      // qkv hi/lo (bf16)
__device__ bf16  g_ql [NT * 3 * DD];
__device__ bf16  g_yh [NT * DD];          // LN output hi/lo
__device__ bf16  g_yl [NT * DD];
__device__ bf16  g_ah [NT * DD];          // attention output hi/lo
__device__ bf16  g_al [NT * DD];
__device__ bf16  g_mh [NT * 4 * DD];      // MLP hidden hi/lo
__device__ bf16  g_ml [NT * 4 * DD];
__device__ float g_bn_mean[16];
__device__ float g_bn_rstd[16];
__device__ int   g_seg[GN + 1];

// bf16 hi/lo weights, transposed to [N][K]
__device__ bf16 g_wq_hi [NBLK * 384 * 128];
__device__ bf16 g_wq_lo [NBLK * 384 * 128];
__device__ bf16 g_wo_hi [NBLK * 128 * 128];
__device__ bf16 g_wo_lo [NBLK * 128 * 128];
__device__ bf16 g_wm1_hi[NBLK * 512 * 128];
__device__ bf16 g_wm1_lo[NBLK * 512 * 128];
__device__ bf16 g_wm2_hi[NBLK * 128 * 512];
__device__ bf16 g_wm2_lo[NBLK * 128 * 512];

// ---------------- asm helpers ----------------
__device__ __forceinline__ uint32_t smem_u32(const void* p) {
    uint32_t a;
    asm("{ .reg .u64 t; cvta.to.shared.u64 t, %1; cvt.u32.u64 %0, t; }" : "=r"(a) : "l"(p));
    return a;
}
__device__ __forceinline__ void cp16(uint32_t dst, const void* src) {
    asm volatile("cp.async.cg.shared.global [%0], [%1], 16;" :: "r"(dst), "l"(src));
}
#define CP_COMMIT() asm volatile("cp.async.commit_group;" ::: "memory")
#define CP_WAIT(n)  asm volatile("cp.async.wait_group %0;" :: "n"(n) : "memory")

__device__ __forceinline__ void ldm_x4(uint32_t r[4], uint32_t a) {
    asm volatile("ldmatrix.sync.aligned.m8n8.x4.shared.b16 {%0,%1,%2,%3}, [%4];"
                 : "=r"(r[0]), "=r"(r[1]), "=r"(r[2]), "=r"(r[3]) : "r"(a));
}
__device__ __forceinline__ void ldm_x4_t(uint32_t r[4], uint32_t a) {
    asm volatile("ldmatrix.sync.aligned.m8n8.x4.trans.shared.b16 {%0,%1,%2,%3}, [%4];"
                 : "=r"(r[0]), "=r"(r[1]), "=r"(r[2]), "=r"(r[3]) : "r"(a));
}
__device__ __forceinline__ void mma_bf16(float c[4], const uint32_t a[4],
                                         uint32_t b0, uint32_t b1) {
    asm volatile(
        "mma.sync.aligned.m16n8k16.row.col.f32.bf16.bf16.f32 "
        "{%0,%1,%2,%3}, {%4,%5,%6,%7}, {%8,%9}, {%0,%1,%2,%3};"
        : "+f"(c[0]), "+f"(c[1]), "+f"(c[2]), "+f"(c[3])
        : "r"(a[0]), "r"(a[1]), "r"(a[2]), "r"(a[3]), "r"(b0), "r"(b1));
}

__device__ __forceinline__ void split_bf16(float v, bf16& hi, bf16& lo) {
    hi = __float2bfloat16(v);
    lo = __float2bfloat16(v - __bfloat162float(hi));
}
__device__ __forceinline__ uint32_t pack2(bf16 a, bf16 b) {
    __nv_bfloat162 t = {a, b};
    return *(uint32_t*)&t;
}
__device__ __forceinline__ float fast_gelu(float u) {
    float z = 0.7978845608028654f * (u + 0.044715f * u * u * u);
    float t = 1.f - 2.f / (__expf(2.f * z) + 1.f);
    return 0.5f * u * (1.f + t);
}

// ---------------- BN batch stats ----------------
__global__ void bn_stats_kernel(const float* __restrict__ s, const float* __restrict__ v) {
    int f = blockIdx.x, t = threadIdx.x;
    float sum = 0.f, sq = 0.f;
    for (int i = t; i < NT; i += 256) {
        float x = (f < 13) ? s[i * 13 + f] : v[i * 3 + (f - 13)];
        sum += x; sq += x * x;
    }
    __shared__ float rs[256], rq[256];
    rs[t] = sum; rq[t] = sq;
    __syncthreads();
    for (int st = 128; st > 0; st >>= 1) {
        if (t < st) { rs[t] += rs[t + st]; rq[t] += rq[t + st]; }
        __syncthreads();
    }
    if (t == 0) {
        float m = rs[0] * (1.f / NT);
        float var = rq[0] * (1.f / NT) - m * m;
        g_bn_mean[f] = m;
        g_bn_rstd[f] = rsqrtf(var + EPSV);
    }
}

// ---------------- segment offsets ----------------
__global__ void seg_kernel(const int* __restrict__ bidx) {
    int g = threadIdx.x;
    if (g > GN) return;
    int lo = 0, hi = NT;
    while (lo < hi) {
        int mid = (lo + hi) >> 1;
        if (bidx[mid] < g) lo = mid + 1; else hi = mid;
    }
    g_seg[g] = lo;
}

// ---------------- BN + embed + LN1[0], warp per row ----------------
__global__ __launch_bounds__(256)
void embed_ln_kernel(const float* __restrict__ s, const float* __restrict__ v,
                     const float* __restrict__ gamma, const float* __restrict__ beta,
                     const float* __restrict__ w_in, const float* __restrict__ b_in,
                     const float* __restrict__ gam, const float* __restrict__ bet) {
    int w = threadIdx.x >> 5, lane = threadIdx.x & 31;
    int row = blockIdx.x * 8 + w;
    // lanes 0..15 hold BN-normalized feature
    float xn = 0.f;
    if (lane < 16) {
        float x = (lane < 13) ? s[row * 13 + lane] : v[row * 3 + (lane - 13)];
        xn = (x - g_bn_mean[lane]) * g_bn_rstd[lane] * gamma[lane] + beta[lane];
    }
    float acc[4];
#pragma unroll
    for (int j = 0; j < 4; j++) acc[j] = b_in[lane * 4 + j];
#pragma unroll
    for (int k = 0; k < 16; k++) {
        float xk = __shfl_sync(0xffffffffu, xn, k);
#pragma unroll
        for (int j = 0; j < 4; j++) acc[j] += xk * w_in[k * DD + lane * 4 + j];
    }
    *(float4*)(g_x + (size_t)row * DD + lane * 4) = *(float4*)acc;
    // LN
    float ssum = acc[0] + acc[1] + acc[2] + acc[3];
    float sqs = acc[0]*acc[0] + acc[1]*acc[1] + acc[2]*acc[2] + acc[3]*acc[3];
#pragma unroll
    for (int o = 16; o; o >>= 1) {
        ssum += __shfl_xor_sync(0xffffffffu, ssum, o);
        sqs  += __shfl_xor_sync(0xffffffffu, sqs,  o);
    }
    float m = ssum * (1.f / DD);
    float var = sqs * (1.f / DD) - m * m;
    float r = rsqrtf(var + EPSV);
    float4 gv = *(const float4*)(gam + lane * 4);
    float4 bv = *(const float4*)(bet + lane * 4);
    bf16 h[4], l[4];
    split_bf16((acc[0] - m) * r * gv.x + bv.x, h[0], l[0]);
    split_bf16((acc[1] - m) * r * gv.y + bv.y, h[1], l[1]);
    split_bf16((acc[2] - m) * r * gv.z + bv.z, h[2], l[2]);
    split_bf16((acc[3] - m) * r * gv.w + bv.w, h[3], l[3]);
    *(uint2*)(g_yh + (size_t)row * DD + lane * 4) = *(uint2*)h;
    *(uint2*)(g_yl + (size_t)row * DD + lane * 4) = *(uint2*)l;
}

// ---------------- merged weight prep ----------------
#define WQ_E (384 * 128)
#define WO_E (128 * 128)
#define W1_E (512 * 128)
#define W2_E (128 * 512)
__global__ void wprep_kernel(const float* __restrict__ wq, const float* __restrict__ wo,
                             const float* __restrict__ w1, const float* __restrict__ w2) {
    int idx = blockIdx.x * 256 + threadIdx.x;
    const float* w; bf16 *whi, *wlo; int K, N, li;
    if (idx < NBLK * WQ_E) {
        w = wq; whi = g_wq_hi; wlo = g_wq_lo; K = 128; N = 384; li = idx;
    } else if (idx < NBLK * (WQ_E + WO_E)) {
        w = wo; whi = g_wo_hi; wlo = g_wo_lo; K = 128; N = 128; li = idx - NBLK * WQ_E;
    } else if (idx < NBLK * (WQ_E + WO_E + W1_E)) {
        w = w1; whi = g_wm1_hi; wlo = g_wm1_lo; K = 128; N = 512; li = idx - NBLK * (WQ_E + WO_E);
    } else if (idx < NBLK * (WQ_E + WO_E + W1_E + W2_E)) {
        w = w2; whi = g_wm2_hi; wlo = g_wm2_lo; K = 512; N = 128; li = idx - NBLK * (WQ_E + WO_E + W1_E);
    } else return;
    int k = li % K;
    int n = (li / K) % N;
    int b = li / (K * N);
    float x = w[(size_t)b * K * N + (size_t)k * N + n];
    bf16 hi, lo;
    split_bf16(x, hi, lo);
    whi[li] = hi;
    wlo[li] = lo;
}

// ---------------- mma.sync GEMM, 4-stage cp.async pipeline ----------------
// FUSE: 0 bias->fp32, 1 bias+res->fp32, 2 bias+gelu->hi/lo, 3 bias->hi/lo,
//       4 bias+res->fp32 + fused LayerNorm -> hi/lo (requires Nc==128, n0==0)
#define STG 24576
#define OFF_AH 0
#define OFF_AL 6144
#define OFF_BH 12288
#define OFF_BL 18432
#define GEMM_SMEM (4 * STG)

template <int FUSE>
__global__ __launch_bounds__(256)
void gemm_mma(const bf16* __restrict__ Ahi, const bf16* __restrict__ Alo,
              const bf16* __restrict__ Bhi, const bf16* __restrict__ Blo,
              const float* __restrict__ bias, const float* __restrict__ R,
              float* __restrict__ C, bf16* __restrict__ Chi, bf16* __restrict__ Clo,
              int K, int Nc,
              const float* __restrict__ lngam, const float* __restrict__ lnbet) {
    extern __shared__ char smem[];
    uint32_t sb = smem_u32(smem);
    int tid = threadIdx.x, lane = tid & 31, wid = tid >> 5;
    int wm = wid & 3, wn = wid >> 2;
    int m0 = blockIdx.y * 128, n0 = blockIdx.x * 128;

    int ldrow = tid >> 1, ldhalf = tid & 1;
    const bf16* pAh = Ahi + (size_t)(m0 + ldrow) * K + ldhalf * 8;
    const bf16* pAl = Alo + (size_t)(m0 + ldrow) * K + ldhalf * 8;
    const bf16* pBh = Bhi + (size_t)(n0 + ldrow) * K + ldhalf * 8;
    const bf16* pBl = Blo + (size_t)(n0 + ldrow) * K + ldhalf * 8;
    uint32_t dstb = sb + ldrow * 48 + ldhalf * 16;

    float acc[2][8][4];
#pragma unroll
    for (int i = 0; i < 2; i++)
#pragma unroll
        for (int j = 0; j < 8; j++)
#pragma unroll
            for (int q = 0; q < 4; q++) acc[i][j][q] = 0.f;

    int nsteps = K >> 4;

#pragma unroll
    for (int s = 0; s < 2; s++) {
        if (s < nsteps) {
            uint32_t d = dstb + s * STG;
            int k0 = s << 4;
            cp16(d + OFF_AH, pAh + k0);
            cp16(d + OFF_AL, pAl + k0);
            cp16(d + OFF_BH, pBh + k0);
            cp16(d + OFF_BL, pBl + k0);
        }
        CP_COMMIT();
    }

    uint32_t a_off = (uint32_t)((wm * 32 + (lane & 15)) * 48 + (lane >> 4) * 16);
    uint32_t b_row = (uint32_t)(wn * 64 + (lane & 7) + ((lane >> 4) << 3));
    uint32_t b_off = b_row * 48 + (((lane >> 3) & 1) << 4);

    for (int c = 0; c < nsteps; c++) {
        if (c + 2 < nsteps) {
            int k0 = (c + 2) << 4;
            uint32_t d = dstb + ((c + 2) & 3) * STG;
            cp16(d + OFF_AH, pAh + k0);
            cp16(d + OFF_AL, pAl + k0);
            cp16(d + OFF_BH, pBh + k0);
            cp16(d + OFF_BL, pBl + k0);
        }
        CP_COMMIT();
        CP_WAIT(2);
        __syncthreads();

        uint32_t sA = sb + (c & 3) * STG;
        uint32_t sB = sA + OFF_BH;

        uint32_t ah[2][4], al[2][4];
#pragma unroll
        for (int mt = 0; mt < 2; mt++) {
            uint32_t addr = sA + a_off + mt * 16 * 48;
            ldm_x4(ah[mt], addr + OFF_AH);
            ldm_x4(al[mt], addr + OFF_AL);
        }
        uint32_t bh[8][2], bl[8][2];
#pragma unroll
        for (int g4 = 0; g4 < 4; g4++) {
            uint32_t addr = sB + b_off + g4 * 16 * 48;
            uint32_t t4[4];
            ldm_x4(t4, addr);
            bh[g4 * 2][0] = t4[0]; bh[g4 * 2][1] = t4[1];
            bh[g4 * 2 + 1][0] = t4[2]; bh[g4 * 2 + 1][1] = t4[3];
            ldm_x4(t4, addr + (OFF_BL - OFF_BH));
            bl[g4 * 2][0] = t4[0]; bl[g4 * 2][1] = t4[1];
            bl[g4 * 2 + 1][0] = t4[2]; bl[g4 * 2 + 1][1] = t4[3];
        }
#pragma unroll
        for (int mt = 0; mt < 2; mt++)
#pragma unroll
            for (int nt = 0; nt < 8; nt++) {
                mma_bf16(acc[mt][nt], ah[mt], bh[nt][0], bh[nt][1]);
                mma_bf16(acc[mt][nt], ah[mt], bl[nt][0], bl[nt][1]);
                mma_bf16(acc[mt][nt], al[mt], bh[nt][0], bh[nt][1]);
            }
    }

    float* xbuf = (float*)smem;   // FUSE=4: [128][132] fp32 residual tile
    if (FUSE == 4) __syncthreads();   // all ldmatrix reads done before reuse

    int lane4 = lane >> 2, lanem = (lane & 3) * 2;
#pragma unroll
    for (int mt = 0; mt < 2; mt++) {
#pragma unroll
        for (int nt = 0; nt < 8; nt++) {
            int col = n0 + wn * 64 + nt * 8 + lanem;
            int r0 = m0 + wm * 32 + mt * 16 + lane4;
            float b0 = bias[col], b1 = bias[col + 1];
#pragma unroll
            for (int half = 0; half < 2; half++) {
                int r = r0 + half * 8;
                float v0 = acc[mt][nt][half * 2 + 0] + b0;
                float v1 = acc[mt][nt][half * 2 + 1] + b1;
                size_t o = (size_t)r * Nc + col;
                if (FUSE == 1 || FUSE == 4) {
                    float2 rr = *(const float2*)(R + o);
                    v0 += rr.x; v1 += rr.y;
                }
                if (FUSE == 2 || FUSE == 3) {
                    if (FUSE == 2) {
                        v0 = fast_gelu(v0);
                        v1 = fast_gelu(v1);
                    }
                    bf16 h0, l0, h1, l1;
                    split_bf16(v0, h0, l0);
                    split_bf16(v1, h1, l1);
                    *(uint32_t*)(Chi + o) = pack2(h0, h1);
                    *(uint32_t*)(Clo + o) = pack2(l0, l1);
                } else {
                    float2 ov = {v0, v1};
                    *(float2*)(C + o) = ov;
                    if (FUSE == 4) {
                        xbuf[(r - m0) * 132 + col] = v0;
                        xbuf[(r - m0) * 132 + col + 1] = v1;
                    }
                }
            }
        }
    }

    if (FUSE == 4) {
        __syncthreads();
        // warp-per-row LN over the fp32 tile -> Chi/Clo (g_yh/g_yl)
#pragma unroll
        for (int rr = wid; rr < 128; rr += 8) {
            float4 xv = *(float4*)(xbuf + rr * 132 + lane * 4);
            float s = xv.x + xv.y + xv.z + xv.w;
            float sq = xv.x*xv.x + xv.y*xv.y + xv.z*xv.z + xv.w*xv.w;
#pragma unroll
            for (int o = 16; o; o >>= 1) {
                s  += __shfl_xor_sync(0xffffffffu, s,  o);
                sq += __shfl_xor_sync(0xffffffffu, sq, o);
            }
            float m = s * (1.f / DD);
            float var = sq * (1.f / DD) - m * m;
            float rcp = rsqrtf(var + EPSV);
            float4 gv = *(const float4*)(lngam + lane * 4);
            float4 bv = *(const float4*)(lnbet + lane * 4);
            bf16 h[4], l[4];
            split_bf16((xv.x - m) * rcp * gv.x + bv.x, h[0], l[0]);
            split_bf16((xv.y - m) * rcp * gv.y + bv.y, h[1], l[1]);
            split_bf16((xv.z - m) * rcp * gv.z + bv.z, h[2], l[2]);
            split_bf16((xv.w - m) * rcp * gv.w + bv.w, h[3], l[3]);
            size_t off = (size_t)(m0 + rr) * DD + lane * 4;
            *(uint2*)(Chi + off) = *(uint2*)h;
            *(uint2*)(Clo + off) = *(uint2*)l;
        }
    }
}

// ---------------- flash segment attention (unchanged from R5) ----------------
#define AT_ROWB 80
#define AT_ARR  (MAXL * AT_ROWB)
#define AT_SMEM (4 * AT_ARR)

__global__ __launch_bounds__(256)
void attn_flash() {
    extern __shared__ char sm[];
    bf16* sKh = (bf16*)sm;
    bf16* sKl = (bf16*)(sm + AT_ARR);
    bf16* sVh = (bf16*)(sm + 2 * AT_ARR);
    bf16* sVl = (bf16*)(sm + 3 * AT_ARR);

    int g = blockIdx.x, h = blockIdx.y;
    int start = g_seg[g];
    int cnt = g_seg[g + 1] - start;
    if (cnt <= 0) return;
    if (cnt > MAXL) cnt = MAXL;
    int tid = threadIdx.x, lane = tid & 31, wid = tid >> 5;
    int tiles = (cnt + 15) >> 4;
    int ncols = tiles << 4;

    uint32_t aKh = smem_u32(sKh), aKl = smem_u32(sKl);
    uint32_t aVh = smem_u32(sVh), aVl = smem_u32(sVl);

    {
        uint4 z = {0, 0, 0, 0};
        int npad = (ncols - cnt) * 4;
        for (int idx = tid; idx < npad; idx += 256) {
            int j = cnt + (idx >> 2), c = idx & 3;
            int o = j * AT_ROWB + c * 16;
            *(uint4*)((char*)sKh + o) = z;
            *(uint4*)((char*)sKl + o) = z;
            *(uint4*)((char*)sVh + o) = z;
            *(uint4*)((char*)sVl + o) = z;
        }
    }
    for (int idx = tid; idx < cnt * 4; idx += 256) {
        int j = idx >> 2, c = idx & 3;
        size_t base = (size_t)(start + j) * 384 + h * 32 + c * 8;
        uint32_t d = (uint32_t)(j * AT_ROWB + c * 16);
        cp16(aKh + d, g_qh + base + 128);
        cp16(aKl + d, g_ql + base + 128);
        cp16(aVh + d, g_qh + base + 256);
        cp16(aVl + d, g_ql + base + 256);
    }
    CP_COMMIT();
    CP_WAIT(0);
    __syncthreads();

    const float scale = 0.17677669529663687f;
    int fr = lane >> 2, fc = (lane & 3) * 2;
    uint32_t kb_row = (uint32_t)((lane & 7) + ((lane >> 4) << 3));
    uint32_t kb_off = kb_row * AT_ROWB + (((lane >> 3) & 1) << 4);
    uint32_t vt_off = (uint32_t)((lane & 15) * AT_ROWB + ((lane >> 4) << 4));

    for (int mt = wid; mt < tiles; mt += 8) {
        uint32_t qh[2][4], ql[2][4];
        {
            int r1 = start + (mt << 4) + fr, r2 = r1 + 8;
            if (r1 >= NT) r1 = NT - 1;
            if (r2 >= NT) r2 = NT - 1;
            const bf16* q1h = g_qh + (size_t)r1 * 384 + h * 32;
            const bf16* q2h = g_qh + (size_t)r2 * 384 + h * 32;
            const bf16* q1l = g_ql + (size_t)r1 * 384 + h * 32;
            const bf16* q2l = g_ql + (size_t)r2 * 384 + h * 32;
#pragma unroll
            for (int ks = 0; ks < 2; ks++) {
                int d0 = ks * 16 + fc, d8 = d0 + 8;
                qh[ks][0] = *(const uint32_t*)(q1h + d0);
                qh[ks][1] = *(const uint32_t*)(q2h + d0);
                qh[ks][2] = *(const uint32_t*)(q1h + d8);
                qh[ks][3] = *(const uint32_t*)(q2h + d8);
                ql[ks][0] = *(const uint32_t*)(q1l + d0);
                ql[ks][1] = *(const uint32_t*)(q2l + d0);
                ql[ks][2] = *(const uint32_t*)(q1l + d8);
                ql[ks][3] = *(const uint32_t*)(q2l + d8);
            }
        }

        float o[4][4];
#pragma unroll
        for (int i = 0; i < 4; i++)
#pragma unroll
            for (int q = 0; q < 4; q++) o[i][q] = 0.f;
        float m_r = -1e30f, m_r8 = -1e30f;
        float l_r = 0.f, l_r8 = 0.f;

        for (int kt = 0; kt < tiles; kt++) {
            float sacc[2][4];
#pragma unroll
            for (int i = 0; i < 2; i++)
#pragma unroll
                for (int q = 0; q < 4; q++) sacc[i][q] = 0.f;
            {
                uint32_t bhf[2][2][2], blf[2][2][2];
#pragma unroll
                for (int ks = 0; ks < 2; ks++) {
                    uint32_t ad = (uint32_t)(kt * 16 * AT_ROWB) + kb_off + ks * 32;
                    uint32_t t4[4];
                    ldm_x4(t4, aKh + ad);
                    bhf[ks][0][0] = t4[0]; bhf[ks][0][1] = t4[1];
                    bhf[ks][1][0] = t4[2]; bhf[ks][1][1] = t4[3];
                    ldm_x4(t4, aKl + ad);
                    blf[ks][0][0] = t4[0]; blf[ks][0][1] = t4[1];
                    blf[ks][1][0] = t4[2]; blf[ks][1][1] = t4[3];
                }
#pragma unroll
                for (int n8 = 0; n8 < 2; n8++)
#pragma unroll
                    for (int ks = 0; ks < 2; ks++) {
                        mma_bf16(sacc[n8], qh[ks], bhf[ks][n8][0], bhf[ks][n8][1]);
                        mma_bf16(sacc[n8], qh[ks], blf[ks][n8][0], blf[ks][n8][1]);
                        mma_bf16(sacc[n8], ql[ks], bhf[ks][n8][0], bhf[ks][n8][1]);
                    }
            }
            float sv[2][4];
#pragma unroll
            for (int n8 = 0; n8 < 2; n8++)
#pragma unroll
                for (int q = 0; q < 4; q++) {
                    int col = kt * 16 + n8 * 8 + fc + (q & 1);
                    sv[n8][q] = (col < cnt) ? sacc[n8][q] * scale : -1e30f;
                }
            float tm_r  = fmaxf(fmaxf(sv[0][0], sv[0][1]), fmaxf(sv[1][0], sv[1][1]));
            float tm_r8 = fmaxf(fmaxf(sv[0][2], sv[0][3]), fmaxf(sv[1][2], sv[1][3]));
#pragma unroll
            for (int oX = 1; oX <= 2; oX <<= 1) {
                tm_r  = fmaxf(tm_r,  __shfl_xor_sync(0xffffffffu, tm_r,  oX));
                tm_r8 = fmaxf(tm_r8, __shfl_xor_sync(0xffffffffu, tm_r8, oX));
            }
            float Mn_r = fmaxf(m_r, tm_r), Mn_r8 = fmaxf(m_r8, tm_r8);
            float cr = __expf(m_r - Mn_r), cr8 = __expf(m_r8 - Mn_r8);
            m_r = Mn_r; m_r8 = Mn_r8;
            float p[2][4];
#pragma unroll
            for (int n8 = 0; n8 < 2; n8++) {
                p[n8][0] = __expf(sv[n8][0] - Mn_r);
                p[n8][1] = __expf(sv[n8][1] - Mn_r);
                p[n8][2] = __expf(sv[n8][2] - Mn_r8);
                p[n8][3] = __expf(sv[n8][3] - Mn_r8);
            }
            l_r  = l_r  * cr  + p[0][0] + p[0][1] + p[1][0] + p[1][1];
            l_r8 = l_r8 * cr8 + p[0][2] + p[0][3] + p[1][2] + p[1][3];
#pragma unroll
            for (int nn = 0; nn < 4; nn++) {
                o[nn][0] *= cr;  o[nn][1] *= cr;
                o[nn][2] *= cr8; o[nn][3] *= cr8;
            }
            uint32_t pa[4], pl[4];
            {
                bf16 h0, l0, h1, l1;
                split_bf16(p[0][0], h0, l0); split_bf16(p[0][1], h1, l1);
                pa[0] = pack2(h0, h1); pl[0] = pack2(l0, l1);
                split_bf16(p[0][2], h0, l0); split_bf16(p[0][3], h1, l1);
                pa[1] = pack2(h0, h1); pl[1] = pack2(l0, l1);
                split_bf16(p[1][0], h0, l0); split_bf16(p[1][1], h1, l1);
                pa[2] = pack2(h0, h1); pl[2] = pack2(l0, l1);
                split_bf16(p[1][2], h0, l0); split_bf16(p[1][3], h1, l1);
                pa[3] = pack2(h0, h1); pl[3] = pack2(l0, l1);
            }
            uint32_t vhf[4][2], vlf[4][2];
#pragma unroll
            for (int cc = 0; cc < 2; cc++) {
                uint32_t ad = (uint32_t)(kt * 16 * AT_ROWB) + vt_off + cc * 32;
                uint32_t t4[4];
                ldm_x4_t(t4, aVh + ad);
                vhf[cc * 2][0] = t4[0]; vhf[cc * 2][1] = t4[1];
                vhf[cc * 2 + 1][0] = t4[2]; vhf[cc * 2 + 1][1] = t4[3];
                ldm_x4_t(t4, aVl + ad);
                vlf[cc * 2][0] = t4[0]; vlf[cc * 2][1] = t4[1];
                vlf[cc * 2 + 1][0] = t4[2]; vlf[cc * 2 + 1][1] = t4[3];
            }
#pragma unroll
            for (int nn = 0; nn < 4; nn++) {
                mma_bf16(o[nn], pa, vhf[nn][0], vhf[nn][1]);
                mma_bf16(o[nn], pa, vlf[nn][0], vlf[nn][1]);
                mma_bf16(o[nn], pl, vhf[nn][0], vhf[nn][1]);
            }
        }

#pragma unroll
        for (int oX = 1; oX <= 2; oX <<= 1) {
            l_r  += __shfl_xor_sync(0xffffffffu, l_r,  oX);
            l_r8 += __shfl_xor_sync(0xffffffffu, l_r8, oX);
        }
        float i1 = 1.f / l_r, i2 = 1.f / l_r8;
        int lr1 = (mt << 4) + fr, lr2 = lr1 + 8;
#pragma unroll
        for (int nn = 0; nn < 4; nn++) {
            int col = h * 32 + nn * 8 + fc;
            if (lr1 < cnt) {
                float v0 = o[nn][0] * i1, v1 = o[nn][1] * i1;
                bf16 h0, l0, h1, l1;
                split_bf16(v0, h0, l0); split_bf16(v1, h1, l1);
                size_t off = (size_t)(start + lr1) * DD + col;
                *(uint32_t*)(g_ah + off) = pack2(h0, h1);
                *(uint32_t*)(g_al + off) = pack2(l0, l1);
            }
            if (lr2 < cnt) {
                float v0 = o[nn][2] * i2, v1 = o[nn][3] * i2;
                bf16 h0, l0, h1, l1;
                split_bf16(v0, h0, l0); split_bf16(v1, h1, l1);
                size_t off = (size_t)(start + lr2) * DD + col;
                *(uint32_t*)(g_ah + off) = pack2(h0, h1);
                *(uint32_t*)(g_al + off) = pack2(l0, l1);
            }
        }
    }
}

// ---------------- final projection ----------------
__global__ void out_kernel(const float* __restrict__ w_out, const float* __restrict__ b_out,
                           float* __restrict__ out) {
    int row = blockIdx.x;
    int t = threadIdx.x;
    float x = __bfloat162float(g_yh[(size_t)row * DD + t]) +
              __bfloat162float(g_yl[(size_t)row * DD + t]);
    float p0 = x * w_out[t * 4 + 0];
    float p1 = x * w_out[t * 4 + 1];
    float p2 = x * w_out[t * 4 + 2];
    float p3 = x * w_out[t * 4 + 3];
#pragma unroll
    for (int o = 16; o; o >>= 1) {
        p0 += __shfl_xor_sync(0xffffffffu, p0, o);
        p1 += __shfl_xor_sync(0xffffffffu, p1, o);
        p2 += __shfl_xor_sync(0xffffffffu, p2, o);
        p3 += __shfl_xor_sync(0xffffffffu, p3, o);
    }
    __shared__ float s4[4][4];
    int w = t >> 5, l = t & 31;
    if (l == 0) { s4[w][0] = p0; s4[w][1] = p1; s4[w][2] = p2; s4[w][3] = p3; }
    __syncthreads();
    if (t < 4) {
        float v = s4[0][t] + s4[1][t] + s4[2][t] + s4[3][t] + b_out[t];
        if (t == 3) v = 1.f / (1.f + __expf(-v));
        out[row * 4 + t] = v;
    }
}

// ---------------- launcher ----------------
extern "C" void kernel_launch(void* const* d_in, const int* in_sizes, int n_in,
                              void* d_out, int out_size) {
    const float* inputs_scalar = (const float*)d_in[0];
    const float* inputs_v      = (const float*)d_in[1];
    const int*   batch_idx     = (const int*)  d_in[2];
    const float* bn_gamma      = (const float*)d_in[3];
    const float* bn_beta       = (const float*)d_in[4];
    const float* w_in          = (const float*)d_in[5];
    const float* b_in          = (const float*)d_in[6];
    const float* ln1_g         = (const float*)d_in[7];
    const float* ln1_b         = (const float*)d_in[8];
    const float* w_qkv         = (const float*)d_in[9];
    const float* b_qkv         = (const float*)d_in[10];
    const float* w_o           = (const float*)d_in[11];
    const float* b_o           = (const float*)d_in[12];
    const float* ln2_g         = (const float*)d_in[13];
    const float* ln2_b         = (const float*)d_in[14];
    const float* w_m1          = (const float*)d_in[15];
    const float* b_m1          = (const float*)d_in[16];
    const float* w_m2          = (const float*)d_in[17];
    const float* b_m2          = (const float*)d_in[18];
    const float* lnf_g         = (const float*)d_in[19];
    const float* lnf_b         = (const float*)d_in[20];
    const float* w_out         = (const float*)d_in[21];
    const float* b_out         = (const float*)d_in[22];
    float* out = (float*)d_out;

    (void)in_sizes; (void)n_in; (void)out_size;

    cudaFuncSetAttribute(attn_flash, cudaFuncAttributeMaxDynamicSharedMemorySize, AT_SMEM);
    cudaFuncSetAttribute(gemm_mma<1>, cudaFuncAttributeMaxDynamicSharedMemorySize, GEMM_SMEM);
    cudaFuncSetAttribute(gemm_mma<2>, cudaFuncAttributeMaxDynamicSharedMemorySize, GEMM_SMEM);
    cudaFuncSetAttribute(gemm_mma<3>, cudaFuncAttributeMaxDynamicSharedMemorySize, GEMM_SMEM);
    cudaFuncSetAttribute(gemm_mma<4>, cudaFuncAttributeMaxDynamicSharedMemorySize, GEMM_SMEM);

    float* px;
    bf16 *qh, *ql, *yh, *yl, *ah, *al, *mh, *ml;
    cudaGetSymbolAddress((void**)&px, g_x);
    cudaGetSymbolAddress((void**)&qh, g_qh);
    cudaGetSymbolAddress((void**)&ql, g_ql);
    cudaGetSymbolAddress((void**)&yh, g_yh);
    cudaGetSymbolAddress((void**)&yl, g_yl);
    cudaGetSymbolAddress((void**)&ah, g_ah);
    cudaGetSymbolAddress((void**)&al, g_al);
    cudaGetSymbolAddress((void**)&mh, g_mh);
    cudaGetSymbolAddress((void**)&ml, g_ml);
    bf16 *wqh, *wql, *woh, *wol, *w1h, *w1l, *w2h, *w2l;
    cudaGetSymbolAddress((void**)&wqh, g_wq_hi);
    cudaGetSymbolAddress((void**)&wql, g_wq_lo);
    cudaGetSymbolAddress((void**)&woh, g_wo_hi);
    cudaGetSymbolAddress((void**)&wol, g_wo_lo);
    cudaGetSymbolAddress((void**)&w1h, g_wm1_hi);
    cudaGetSymbolAddress((void**)&w1l, g_wm1_lo);
    cudaGetSymbolAddress((void**)&w2h, g_wm2_hi);
    cudaGetSymbolAddress((void**)&w2l, g_wm2_lo);

    int wtotal = NBLK * (WQ_E + WO_E + W1_E + W2_E);
    wprep_kernel<<<(wtotal + 255) / 256, 256>>>(w_qkv, w_o, w_m1, w_m2);

    bn_stats_kernel<<<16, 256>>>(inputs_scalar, inputs_v);
    seg_kernel<<<1, 256>>>(batch_idx);
    embed_ln_kernel<<<NT / 8, 256>>>(inputs_scalar, inputs_v, bn_gamma, bn_beta,
                                     w_in, b_in, ln1_g, ln1_b);

    for (int i = 0; i < NBLK; i++) {
        gemm_mma<3><<<dim3(3, NT / 128), 256, GEMM_SMEM>>>(
            yh, yl, wqh + (size_t)i * WQ_E, wql + (size_t)i * WQ_E,
            b_qkv + i * 3 * DD, nullptr, nullptr, qh, ql, 128, 384, nullptr, nullptr);
        attn_flash<<<dim3(GN, HN), 256, AT_SMEM>>>();
        gemm_mma<4><<<dim3(1, NT / 128), 256, GEMM_SMEM>>>(
            ah, al, woh + (size_t)i * WO_E, wol + (size_t)i * WO_E,
            b_o + i * DD, px, px, yh, yl, 128, 128,
            ln2_g + i * DD, ln2_b + i * DD);
        gemm_mma<2><<<dim3(4, NT / 128), 256, GEMM_SMEM>>>(
            yh, yl, w1h + (size_t)i * W1_E, w1l + (size_t)i * W1_E,
            b_m1 + i * 4 * DD, nullptr, nullptr, mh, ml, 128, 512, nullptr, nullptr);
        const float* ng = (i + 1 < NBLK) ? (ln1_g + (i + 1) * DD) : lnf_g;
        const float* nb = (i + 1 < NBLK) ? (ln1_b + (i + 1) * DD) : lnf_b;
        gemm_mma<4><<<dim3(1, NT / 128), 256, GEMM_SMEM>>>(
            mh, ml, w2h + (size_t)i * W2_E, w2l + (size_t)i * W2_E,
            b_m2 + i * DD, px, px, yh, yl, 512, 128, ng, nb);
    }

    out_kernel<<<NT, 128>>>(w_out, b_out, out);
}

// round 7
// speedup vs baseline: 1.4950x; 1.0745x over previous
#include <cuda_runtime.h>
#include <cuda_bf16.h>
#include <cstdint>
#include <math.h>

#define NT   16384
#define GN   128
#define DD   128
#define HN   4
#define DHD  32
#define NBLK 10
#define MAXL 256
#define EPSV 1e-5f

typedef __nv_bfloat16 bf16;

// ---------------- scratch ----------------
__device__ float g_x  [NT * DD];          // residual stream (fp32)
__device__ bf16  g_qh [NT * 3 * DD];      // qkv hi/lo (bf16)
__device__ bf16  g_ql [NT * 3 * DD];
__device__ bf16  g_yh [NT * DD];          // LN output hi/lo
__device__ bf16  g_yl [NT * DD];
__device__ bf16  g_ah [NT * DD];          // attention output hi/lo
__device__ bf16  g_al [NT * DD];
__device__ bf16  g_mh [NT * 4 * DD];      // MLP hidden hi/lo
__device__ bf16  g_ml [NT * 4 * DD];
__device__ float g_bn_mean[16];
__device__ float g_bn_rstd[16];
__device__ int   g_seg[GN + 1];

// bf16 hi/lo weights, transposed to [N][K]
__device__ bf16 g_wq_hi [NBLK * 384 * 128];
__device__ bf16 g_wq_lo [NBLK * 384 * 128];
__device__ bf16 g_wo_hi [NBLK * 128 * 128];
__device__ bf16 g_wo_lo [NBLK * 128 * 128];
__device__ bf16 g_wm1_hi[NBLK * 512 * 128];
__device__ bf16 g_wm1_lo[NBLK * 512 * 128];
__device__ bf16 g_wm2_hi[NBLK * 128 * 512];
__device__ bf16 g_wm2_lo[NBLK * 128 * 512];

// ---------------- asm helpers ----------------
__device__ __forceinline__ uint32_t smem_u32(const void* p) {
    uint32_t a;
    asm("{ .reg .u64 t; cvta.to.shared.u64 t, %1; cvt.u32.u64 %0, t; }" : "=r"(a) : "l"(p));
    return a;
}
__device__ __forceinline__ void cp16(uint32_t dst, const void* src) {
    asm volatile("cp.async.cg.shared.global [%0], [%1], 16;" :: "r"(dst), "l"(src));
}
#define CP_COMMIT() asm volatile("cp.async.commit_group;" ::: "memory")
#define CP_WAIT(n)  asm volatile("cp.async.wait_group %0;" :: "n"(n) : "memory")

__device__ __forceinline__ void ldm_x4(uint32_t r[4], uint32_t a) {
    asm volatile("ldmatrix.sync.aligned.m8n8.x4.shared.b16 {%0,%1,%2,%3}, [%4];"
                 : "=r"(r[0]), "=r"(r[1]), "=r"(r[2]), "=r"(r[3]) : "r"(a));
}
__device__ __forceinline__ void ldm_x4_t(uint32_t r[4], uint32_t a) {
    asm volatile("ldmatrix.sync.aligned.m8n8.x4.trans.shared.b16 {%0,%1,%2,%3}, [%4];"
                 : "=r"(r[0]), "=r"(r[1]), "=r"(r[2]), "=r"(r[3]) : "r"(a));
}
__device__ __forceinline__ void mma_bf16(float c[4], const uint32_t a[4],
                                         uint32_t b0, uint32_t b1) {
    asm volatile(
        "mma.sync.aligned.m16n8k16.row.col.f32.bf16.bf16.f32 "
        "{%0,%1,%2,%3}, {%4,%5,%6,%7}, {%8,%9}, {%0,%1,%2,%3};"
        : "+f"(c[0]), "+f"(c[1]), "+f"(c[2]), "+f"(c[3])
        : "r"(a[0]), "r"(a[1]), "r"(a[2]), "r"(a[3]), "r"(b0), "r"(b1));
}

__device__ __forceinline__ void split_bf16(float v, bf16& hi, bf16& lo) {
    hi = __float2bfloat16(v);
    lo = __float2bfloat16(v - __bfloat162float(hi));
}
__device__ __forceinline__ uint32_t pack2(bf16 a, bf16 b) {
    __nv_bfloat162 t = {a, b};
    return *(uint32_t*)&t;
}
__device__ __forceinline__ float fast_gelu(float u) {
    float z = 0.7978845608028654f * (u + 0.044715f * u * u * u);
    float t = 1.f - 2.f / (__expf(2.f * z) + 1.f);
    return 0.5f * u * (1.f + t);
}

// ---------------- BN batch stats ----------------
__global__ void bn_stats_kernel(const float* __restrict__ s, const float* __restrict__ v) {
    int f = blockIdx.x, t = threadIdx.x;
    float sum = 0.f, sq = 0.f;
    for (int i = t; i < NT; i += 256) {
        float x = (f < 13) ? s[i * 13 + f] : v[i * 3 + (f - 13)];
        sum += x; sq += x * x;
    }
    __shared__ float rs[256], rq[256];
    rs[t] = sum; rq[t] = sq;
    __syncthreads();
    for (int st = 128; st > 0; st >>= 1) {
        if (t < st) { rs[t] += rs[t + st]; rq[t] += rq[t + st]; }
        __syncthreads();
    }
    if (t == 0) {
        float m = rs[0] * (1.f / NT);
        float var = rq[0] * (1.f / NT) - m * m;
        g_bn_mean[f] = m;
        g_bn_rstd[f] = rsqrtf(var + EPSV);
    }
}

// ---------------- segment offsets ----------------
__global__ void seg_kernel(const int* __restrict__ bidx) {
    int g = threadIdx.x;
    if (g > GN) return;
    int lo = 0, hi = NT;
    while (lo < hi) {
        int mid = (lo + hi) >> 1;
        if (bidx[mid] < g) lo = mid + 1; else hi = mid;
    }
    g_seg[g] = lo;
}

// ---------------- BN + embed + LN1[0], warp per row ----------------
__global__ __launch_bounds__(256)
void embed_ln_kernel(const float* __restrict__ s, const float* __restrict__ v,
                     const float* __restrict__ gamma, const float* __restrict__ beta,
                     const float* __restrict__ w_in, const float* __restrict__ b_in,
                     const float* __restrict__ gam, const float* __restrict__ bet) {
    int w = threadIdx.x >> 5, lane = threadIdx.x & 31;
    int row = blockIdx.x * 8 + w;
    float xn = 0.f;
    if (lane < 16) {
        float x = (lane < 13) ? s[row * 13 + lane] : v[row * 3 + (lane - 13)];
        xn = (x - g_bn_mean[lane]) * g_bn_rstd[lane] * gamma[lane] + beta[lane];
    }
    float acc[4];
#pragma unroll
    for (int j = 0; j < 4; j++) acc[j] = b_in[lane * 4 + j];
#pragma unroll
    for (int k = 0; k < 16; k++) {
        float xk = __shfl_sync(0xffffffffu, xn, k);
#pragma unroll
        for (int j = 0; j < 4; j++) acc[j] += xk * w_in[k * DD + lane * 4 + j];
    }
    *(float4*)(g_x + (size_t)row * DD + lane * 4) = *(float4*)acc;
    float ssum = acc[0] + acc[1] + acc[2] + acc[3];
    float sqs = acc[0]*acc[0] + acc[1]*acc[1] + acc[2]*acc[2] + acc[3]*acc[3];
#pragma unroll
    for (int o = 16; o; o >>= 1) {
        ssum += __shfl_xor_sync(0xffffffffu, ssum, o);
        sqs  += __shfl_xor_sync(0xffffffffu, sqs,  o);
    }
    float m = ssum * (1.f / DD);
    float var = sqs * (1.f / DD) - m * m;
    float r = rsqrtf(var + EPSV);
    float4 gv = *(const float4*)(gam + lane * 4);
    float4 bv = *(const float4*)(bet + lane * 4);
    bf16 h[4], l[4];
    split_bf16((acc[0] - m) * r * gv.x + bv.x, h[0], l[0]);
    split_bf16((acc[1] - m) * r * gv.y + bv.y, h[1], l[1]);
    split_bf16((acc[2] - m) * r * gv.z + bv.z, h[2], l[2]);
    split_bf16((acc[3] - m) * r * gv.w + bv.w, h[3], l[3]);
    *(uint2*)(g_yh + (size_t)row * DD + lane * 4) = *(uint2*)h;
    *(uint2*)(g_yl + (size_t)row * DD + lane * 4) = *(uint2*)l;
}

// ---------------- merged weight prep ----------------
#define WQ_E (384 * 128)
#define WO_E (128 * 128)
#define W1_E (512 * 128)
#define W2_E (128 * 512)
__global__ void wprep_kernel(const float* __restrict__ wq, const float* __restrict__ wo,
                             const float* __restrict__ w1, const float* __restrict__ w2) {
    int idx = blockIdx.x * 256 + threadIdx.x;
    const float* w; bf16 *whi, *wlo; int K, N, li;
    if (idx < NBLK * WQ_E) {
        w = wq; whi = g_wq_hi; wlo = g_wq_lo; K = 128; N = 384; li = idx;
    } else if (idx < NBLK * (WQ_E + WO_E)) {
        w = wo; whi = g_wo_hi; wlo = g_wo_lo; K = 128; N = 128; li = idx - NBLK * WQ_E;
    } else if (idx < NBLK * (WQ_E + WO_E + W1_E)) {
        w = w1; whi = g_wm1_hi; wlo = g_wm1_lo; K = 128; N = 512; li = idx - NBLK * (WQ_E + WO_E);
    } else if (idx < NBLK * (WQ_E + WO_E + W1_E + W2_E)) {
        w = w2; whi = g_wm2_hi; wlo = g_wm2_lo; K = 512; N = 128; li = idx - NBLK * (WQ_E + WO_E + W1_E);
    } else return;
    int k = li % K;
    int n = (li / K) % N;
    int b = li / (K * N);
    float x = w[(size_t)b * K * N + (size_t)k * N + n];
    bf16 hi, lo;
    split_bf16(x, hi, lo);
    whi[li] = hi;
    wlo[li] = lo;
}

// ---------------- mma.sync GEMM: BM=64, BN=128, BK=16, 4-stage cp.async ----------------
// 8 warps as 2(m) x 4(n); warp tile 32x32 = acc[2][4][4].
// FUSE: 0 bias->fp32, 1 bias+res->fp32, 2 bias+gelu->hi/lo, 3 bias->hi/lo,
//       4 bias+res->fp32 + fused LayerNorm -> hi/lo (requires Nc==128, n0==0)
#define STG 18432
#define OFF_AH 0
#define OFF_AL 3072
#define OFF_BH 6144
#define OFF_BL 12288
#define GEMM_SMEM (4 * STG)   // 73728

template <int FUSE>
__global__ __launch_bounds__(256, 3)
void gemm_mma(const bf16* __restrict__ Ahi, const bf16* __restrict__ Alo,
              const bf16* __restrict__ Bhi, const bf16* __restrict__ Blo,
              const float* __restrict__ bias, const float* __restrict__ R,
              float* __restrict__ C, bf16* __restrict__ Chi, bf16* __restrict__ Clo,
              int K, int Nc,
              const float* __restrict__ lngam, const float* __restrict__ lnbet) {
    extern __shared__ char smem[];
    uint32_t sb = smem_u32(smem);
    int tid = threadIdx.x, lane = tid & 31, wid = tid >> 5;
    int wm = wid & 1, wn = wid >> 1;          // 2 x 4 warp grid, warp tile 32x32
    int m0 = blockIdx.y * 64, n0 = blockIdx.x * 128;

    int ldrow = tid >> 1, ldhalf = tid & 1;
    const bf16* pAh = Ahi + (size_t)(m0 + ldrow) * K + ldhalf * 8;   // valid tid<128
    const bf16* pAl = Alo + (size_t)(m0 + ldrow) * K + ldhalf * 8;
    const bf16* pBh = Bhi + (size_t)(n0 + ldrow) * K + ldhalf * 8;
    const bf16* pBl = Blo + (size_t)(n0 + ldrow) * K + ldhalf * 8;
    uint32_t dstL = sb + ldrow * 48 + ldhalf * 16;
    bool doA = (tid < 128);

    float acc[2][4][4];
#pragma unroll
    for (int i = 0; i < 2; i++)
#pragma unroll
        for (int j = 0; j < 4; j++)
#pragma unroll
            for (int q = 0; q < 4; q++) acc[i][j][q] = 0.f;

    int nsteps = K >> 4;

#pragma unroll
    for (int s = 0; s < 2; s++) {
        if (s < nsteps) {
            uint32_t d = dstL + s * STG;
            int k0 = s << 4;
            if (doA) {
                cp16(d + OFF_AH, pAh + k0);
                cp16(d + OFF_AL, pAl + k0);
            }
            cp16(d + OFF_BH, pBh + k0);
            cp16(d + OFF_BL, pBl + k0);
        }
        CP_COMMIT();
    }

    uint32_t a_off = (uint32_t)((wm * 32 + (lane & 15)) * 48 + (lane >> 4) * 16);
    uint32_t b_row = (uint32_t)(wn * 32 + (lane & 7) + ((lane >> 4) << 3));
    uint32_t b_off = b_row * 48 + (((lane >> 3) & 1) << 4);

    for (int c = 0; c < nsteps; c++) {
        if (c + 2 < nsteps) {
            int k0 = (c + 2) << 4;
            uint32_t d = dstL + ((c + 2) & 3) * STG;
            if (doA) {
                cp16(d + OFF_AH, pAh + k0);
                cp16(d + OFF_AL, pAl + k0);
            }
            cp16(d + OFF_BH, pBh + k0);
            cp16(d + OFF_BL, pBl + k0);
        }
        CP_COMMIT();
        CP_WAIT(2);
        __syncthreads();

        uint32_t sA = sb + (c & 3) * STG;
        uint32_t sB = sA + OFF_BH;

        uint32_t ah[2][4], al[2][4];
#pragma unroll
        for (int mt = 0; mt < 2; mt++) {
            uint32_t addr = sA + a_off + mt * 16 * 48;
            ldm_x4(ah[mt], addr + OFF_AH);
            ldm_x4(al[mt], addr + (OFF_AL - OFF_AH));
        }
        uint32_t bh[4][2], bl[4][2];
#pragma unroll
        for (int g4 = 0; g4 < 2; g4++) {
            uint32_t addr = sB + b_off + g4 * 16 * 48;
            uint32_t t4[4];
            ldm_x4(t4, addr);
            bh[g4 * 2][0] = t4[0]; bh[g4 * 2][1] = t4[1];
            bh[g4 * 2 + 1][0] = t4[2]; bh[g4 * 2 + 1][1] = t4[3];
            ldm_x4(t4, addr + (OFF_BL - OFF_BH));
            bl[g4 * 2][0] = t4[0]; bl[g4 * 2][1] = t4[1];
            bl[g4 * 2 + 1][0] = t4[2]; bl[g4 * 2 + 1][1] = t4[3];
        }
#pragma unroll
        for (int mt = 0; mt < 2; mt++)
#pragma unroll
            for (int nt = 0; nt < 4; nt++) {
                mma_bf16(acc[mt][nt], ah[mt], bh[nt][0], bh[nt][1]);
                mma_bf16(acc[mt][nt], ah[mt], bl[nt][0], bl[nt][1]);
                mma_bf16(acc[mt][nt], al[mt], bh[nt][0], bh[nt][1]);
            }
    }

    float* xbuf = (float*)smem;   // FUSE=4: [64][132] fp32 residual tile
    if (FUSE == 4) __syncthreads();

    int lane4 = lane >> 2, lanem = (lane & 3) * 2;
#pragma unroll
    for (int mt = 0; mt < 2; mt++) {
#pragma unroll
        for (int nt = 0; nt < 4; nt++) {
            int col = n0 + wn * 32 + nt * 8 + lanem;
            int r0 = m0 + wm * 32 + mt * 16 + lane4;
            float b0 = bias[col], b1 = bias[col + 1];
#pragma unroll
            for (int half = 0; half < 2; half++) {
                int r = r0 + half * 8;
                float v0 = acc[mt][nt][half * 2 + 0] + b0;
                float v1 = acc[mt][nt][half * 2 + 1] + b1;
                size_t o = (size_t)r * Nc + col;
                if (FUSE == 1 || FUSE == 4) {
                    float2 rr = *(const float2*)(R + o);
                    v0 += rr.x; v1 += rr.y;
                }
                if (FUSE == 2 || FUSE == 3) {
                    if (FUSE == 2) {
                        v0 = fast_gelu(v0);
                        v1 = fast_gelu(v1);
                    }
                    bf16 h0, l0, h1, l1;
                    split_bf16(v0, h0, l0);
                    split_bf16(v1, h1, l1);
                    *(uint32_t*)(Chi + o) = pack2(h0, h1);
                    *(uint32_t*)(Clo + o) = pack2(l0, l1);
                } else {
                    float2 ov = {v0, v1};
                    *(float2*)(C + o) = ov;
                    if (FUSE == 4) {
                        xbuf[(r - m0) * 132 + col] = v0;
                        xbuf[(r - m0) * 132 + col + 1] = v1;
                    }
                }
            }
        }
    }

    if (FUSE == 4) {
        __syncthreads();
#pragma unroll
        for (int rr = wid; rr < 64; rr += 8) {
            float4 xv = *(float4*)(xbuf + rr * 132 + lane * 4);
            float s = xv.x + xv.y + xv.z + xv.w;
            float sq = xv.x*xv.x + xv.y*xv.y + xv.z*xv.z + xv.w*xv.w;
#pragma unroll
            for (int o = 16; o; o >>= 1) {
                s  += __shfl_xor_sync(0xffffffffu, s,  o);
                sq += __shfl_xor_sync(0xffffffffu, sq, o);
            }
            float m = s * (1.f / DD);
            float var = sq * (1.f / DD) - m * m;
            float rcp = rsqrtf(var + EPSV);
            float4 gv = *(const float4*)(lngam + lane * 4);
            float4 bv = *(const float4*)(lnbet + lane * 4);
            bf16 h[4], l[4];
            split_bf16((xv.x - m) * rcp * gv.x + bv.x, h[0], l[0]);
            split_bf16((xv.y - m) * rcp * gv.y + bv.y, h[1], l[1]);
            split_bf16((xv.z - m) * rcp * gv.z + bv.z, h[2], l[2]);
            split_bf16((xv.w - m) * rcp * gv.w + bv.w, h[3], l[3]);
            size_t off = (size_t)(m0 + rr) * DD + lane * 4;
            *(uint2*)(Chi + off) = *(uint2*)h;
            *(uint2*)(Clo + off) = *(uint2*)l;
        }
    }
}

// ---------------- flash segment attention (unchanged from R5) ----------------
#define AT_ROWB 80
#define AT_ARR  (MAXL * AT_ROWB)
#define AT_SMEM (4 * AT_ARR)

__global__ __launch_bounds__(256)
void attn_flash() {
    extern __shared__ char sm[];
    bf16* sKh = (bf16*)sm;
    bf16* sKl = (bf16*)(sm + AT_ARR);
    bf16* sVh = (bf16*)(sm + 2 * AT_ARR);
    bf16* sVl = (bf16*)(sm + 3 * AT_ARR);

    int g = blockIdx.x, h = blockIdx.y;
    int start = g_seg[g];
    int cnt = g_seg[g + 1] - start;
    if (cnt <= 0) return;
    if (cnt > MAXL) cnt = MAXL;
    int tid = threadIdx.x, lane = tid & 31, wid = tid >> 5;
    int tiles = (cnt + 15) >> 4;
    int ncols = tiles << 4;

    uint32_t aKh = smem_u32(sKh), aKl = smem_u32(sKl);
    uint32_t aVh = smem_u32(sVh), aVl = smem_u32(sVl);

    {
        uint4 z = {0, 0, 0, 0};
        int npad = (ncols - cnt) * 4;
        for (int idx = tid; idx < npad; idx += 256) {
            int j = cnt + (idx >> 2), c = idx & 3;
            int o = j * AT_ROWB + c * 16;
            *(uint4*)((char*)sKh + o) = z;
            *(uint4*)((char*)sKl + o) = z;
            *(uint4*)((char*)sVh + o) = z;
            *(uint4*)((char*)sVl + o) = z;
        }
    }
    for (int idx = tid; idx < cnt * 4; idx += 256) {
        int j = idx >> 2, c = idx & 3;
        size_t base = (size_t)(start + j) * 384 + h * 32 + c * 8;
        uint32_t d = (uint32_t)(j * AT_ROWB + c * 16);
        cp16(aKh + d, g_qh + base + 128);
        cp16(aKl + d, g_ql + base + 128);
        cp16(aVh + d, g_qh + base + 256);
        cp16(aVl + d, g_ql + base + 256);
    }
    CP_COMMIT();
    CP_WAIT(0);
    __syncthreads();

    const float scale = 0.17677669529663687f;
    int fr = lane >> 2, fc = (lane & 3) * 2;
    uint32_t kb_row = (uint32_t)((lane & 7) + ((lane >> 4) << 3));
    uint32_t kb_off = kb_row * AT_ROWB + (((lane >> 3) & 1) << 4);
    uint32_t vt_off = (uint32_t)((lane & 15) * AT_ROWB + ((lane >> 4) << 4));

    for (int mt = wid; mt < tiles; mt += 8) {
        uint32_t qh[2][4], ql[2][4];
        {
            int r1 = start + (mt << 4) + fr, r2 = r1 + 8;
            if (r1 >= NT) r1 = NT - 1;
            if (r2 >= NT) r2 = NT - 1;
            const bf16* q1h = g_qh + (size_t)r1 * 384 + h * 32;
            const bf16* q2h = g_qh + (size_t)r2 * 384 + h * 32;
            const bf16* q1l = g_ql + (size_t)r1 * 384 + h * 32;
            const bf16* q2l = g_ql + (size_t)r2 * 384 + h * 32;
#pragma unroll
            for (int ks = 0; ks < 2; ks++) {
                int d0 = ks * 16 + fc, d8 = d0 + 8;
                qh[ks][0] = *(const uint32_t*)(q1h + d0);
                qh[ks][1] = *(const uint32_t*)(q2h + d0);
                qh[ks][2] = *(const uint32_t*)(q1h + d8);
                qh[ks][3] = *(const uint32_t*)(q2h + d8);
                ql[ks][0] = *(const uint32_t*)(q1l + d0);
                ql[ks][1] = *(const uint32_t*)(q2l + d0);
                ql[ks][2] = *(const uint32_t*)(q1l + d8);
                ql[ks][3] = *(const uint32_t*)(q2l + d8);
            }
        }

        float o[4][4];
#pragma unroll
        for (int i = 0; i < 4; i++)
#pragma unroll
            for (int q = 0; q < 4; q++) o[i][q] = 0.f;
        float m_r = -1e30f, m_r8 = -1e30f;
        float l_r = 0.f, l_r8 = 0.f;

        for (int kt = 0; kt < tiles; kt++) {
            float sacc[2][4];
#pragma unroll
            for (int i = 0; i < 2; i++)
#pragma unroll
                for (int q = 0; q < 4; q++) sacc[i][q] = 0.f;
            {
                uint32_t bhf[2][2][2], blf[2][2][2];
#pragma unroll
                for (int ks = 0; ks < 2; ks++) {
                    uint32_t ad = (uint32_t)(kt * 16 * AT_ROWB) + kb_off + ks * 32;
                    uint32_t t4[4];
                    ldm_x4(t4, aKh + ad);
                    bhf[ks][0][0] = t4[0]; bhf[ks][0][1] = t4[1];
                    bhf[ks][1][0] = t4[2]; bhf[ks][1][1] = t4[3];
                    ldm_x4(t4, aKl + ad);
                    blf[ks][0][0] = t4[0]; blf[ks][0][1] = t4[1];
                    blf[ks][1][0] = t4[2]; blf[ks][1][1] = t4[3];
                }
#pragma unroll
                for (int n8 = 0; n8 < 2; n8++)
#pragma unroll
                    for (int ks = 0; ks < 2; ks++) {
                        mma_bf16(sacc[n8], qh[ks], bhf[ks][n8][0], bhf[ks][n8][1]);
                        mma_bf16(sacc[n8], qh[ks], blf[ks][n8][0], blf[ks][n8][1]);
                        mma_bf16(sacc[n8], ql[ks], bhf[ks][n8][0], bhf[ks][n8][1]);
                    }
            }
            float sv[2][4];
#pragma unroll
            for (int n8 = 0; n8 < 2; n8++)
#pragma unroll
                for (int q = 0; q < 4; q++) {
                    int col = kt * 16 + n8 * 8 + fc + (q & 1);
                    sv[n8][q] = (col < cnt) ? sacc[n8][q] * scale : -1e30f;
                }
            float tm_r  = fmaxf(fmaxf(sv[0][0], sv[0][1]), fmaxf(sv[1][0], sv[1][1]));
            float tm_r8 = fmaxf(fmaxf(sv[0][2], sv[0][3]), fmaxf(sv[1][2], sv[1][3]));
#pragma unroll
            for (int oX = 1; oX <= 2; oX <<= 1) {
                tm_r  = fmaxf(tm_r,  __shfl_xor_sync(0xffffffffu, tm_r,  oX));
                tm_r8 = fmaxf(tm_r8, __shfl_xor_sync(0xffffffffu, tm_r8, oX));
            }
            float Mn_r = fmaxf(m_r, tm_r), Mn_r8 = fmaxf(m_r8, tm_r8);
            float cr = __expf(m_r - Mn_r), cr8 = __expf(m_r8 - Mn_r8);
            m_r = Mn_r; m_r8 = Mn_r8;
            float p[2][4];
#pragma unroll
            for (int n8 = 0; n8 < 2; n8++) {
                p[n8][0] = __expf(sv[n8][0] - Mn_r);
                p[n8][1] = __expf(sv[n8][1] - Mn_r);
                p[n8][2] = __expf(sv[n8][2] - Mn_r8);
                p[n8][3] = __expf(sv[n8][3] - Mn_r8);
            }
            l_r  = l_r  * cr  + p[0][0] + p[0][1] + p[1][0] + p[1][1];
            l_r8 = l_r8 * cr8 + p[0][2] + p[0][3] + p[1][2] + p[1][3];
#pragma unroll
            for (int nn = 0; nn < 4; nn++) {
                o[nn][0] *= cr;  o[nn][1] *= cr;
                o[nn][2] *= cr8; o[nn][3] *= cr8;
            }
            uint32_t pa[4], pl[4];
            {
                bf16 h0, l0, h1, l1;
                split_bf16(p[0][0], h0, l0); split_bf16(p[0][1], h1, l1);
                pa[0] = pack2(h0, h1); pl[0] = pack2(l0, l1);
                split_bf16(p[0][2], h0, l0); split_bf16(p[0][3], h1, l1);
                pa[1] = pack2(h0, h1); pl[1] = pack2(l0, l1);
                split_bf16(p[1][0], h0, l0); split_bf16(p[1][1], h1, l1);
                pa[2] = pack2(h0, h1); pl[2] = pack2(l0, l1);
                split_bf16(p[1][2], h0, l0); split_bf16(p[1][3], h1, l1);
                pa[3] = pack2(h0, h1); pl[3] = pack2(l0, l1);
            }
            uint32_t vhf[4][2], vlf[4][2];
#pragma unroll
            for (int cc = 0; cc < 2; cc++) {
                uint32_t ad = (uint32_t)(kt * 16 * AT_ROWB) + vt_off + cc * 32;
                uint32_t t4[4];
                ldm_x4_t(t4, aVh + ad);
                vhf[cc * 2][0] = t4[0]; vhf[cc * 2][1] = t4[1];
                vhf[cc * 2 + 1][0] = t4[2]; vhf[cc * 2 + 1][1] = t4[3];
                ldm_x4_t(t4, aVl + ad);
                vlf[cc * 2][0] = t4[0]; vlf[cc * 2][1] = t4[1];
                vlf[cc * 2 + 1][0] = t4[2]; vlf[cc * 2 + 1][1] = t4[3];
            }
#pragma unroll
            for (int nn = 0; nn < 4; nn++) {
                mma_bf16(o[nn], pa, vhf[nn][0], vhf[nn][1]);
                mma_bf16(o[nn], pa, vlf[nn][0], vlf[nn][1]);
                mma_bf16(o[nn], pl, vhf[nn][0], vhf[nn][1]);
            }
        }

#pragma unroll
        for (int oX = 1; oX <= 2; oX <<= 1) {
            l_r  += __shfl_xor_sync(0xffffffffu, l_r,  oX);
            l_r8 += __shfl_xor_sync(0xffffffffu, l_r8, oX);
        }
        float i1 = 1.f / l_r, i2 = 1.f / l_r8;
        int lr1 = (mt << 4) + fr, lr2 = lr1 + 8;
#pragma unroll
        for (int nn = 0; nn < 4; nn++) {
            int col = h * 32 + nn * 8 + fc;
            if (lr1 < cnt) {
                float v0 = o[nn][0] * i1, v1 = o[nn][1] * i1;
                bf16 h0, l0, h1, l1;
                split_bf16(v0, h0, l0); split_bf16(v1, h1, l1);
                size_t off = (size_t)(start + lr1) * DD + col;
                *(uint32_t*)(g_ah + off) = pack2(h0, h1);
                *(uint32_t*)(g_al + off) = pack2(l0, l1);
            }
            if (lr2 < cnt) {
                float v0 = o[nn][2] * i2, v1 = o[nn][3] * i2;
                bf16 h0, l0, h1, l1;
                split_bf16(v0, h0, l0); split_bf16(v1, h1, l1);
                size_t off = (size_t)(start + lr2) * DD + col;
                *(uint32_t*)(g_ah + off) = pack2(h0, h1);
                *(uint32_t*)(g_al + off) = pack2(l0, l1);
            }
        }
    }
}

// ---------------- final projection ----------------
__global__ void out_kernel(const float* __restrict__ w_out, const float* __restrict__ b_out,
                           float* __restrict__ out) {
    int row = blockIdx.x;
    int t = threadIdx.x;
    float x = __bfloat162float(g_yh[(size_t)row * DD + t]) +
              __bfloat162float(g_yl[(size_t)row * DD + t]);
    float p0 = x * w_out[t * 4 + 0];
    float p1 = x * w_out[t * 4 + 1];
    float p2 = x * w_out[t * 4 + 2];
    float p3 = x * w_out[t * 4 + 3];
#pragma unroll
    for (int o = 16; o; o >>= 1) {
        p0 += __shfl_xor_sync(0xffffffffu, p0, o);
        p1 += __shfl_xor_sync(0xffffffffu, p1, o);
        p2 += __shfl_xor_sync(0xffffffffu, p2, o);
        p3 += __shfl_xor_sync(0xffffffffu, p3, o);
    }
    __shared__ float s4[4][4];
    int w = t >> 5, l = t & 31;
    if (l == 0) { s4[w][0] = p0; s4[w][1] = p1; s4[w][2] = p2; s4[w][3] = p3; }
    __syncthreads();
    if (t < 4) {
        float v = s4[0][t] + s4[1][t] + s4[2][t] + s4[3][t] + b_out[t];
        if (t == 3) v = 1.f / (1.f + __expf(-v));
        out[row * 4 + t] = v;
    }
}

// ---------------- launcher ----------------
extern "C" void kernel_launch(void* const* d_in, const int* in_sizes, int n_in,
                              void* d_out, int out_size) {
    const float* inputs_scalar = (const float*)d_in[0];
    const float* inputs_v      = (const float*)d_in[1];
    const int*   batch_idx     = (const int*)  d_in[2];
    const float* bn_gamma      = (const float*)d_in[3];
    const float* bn_beta       = (const float*)d_in[4];
    const float* w_in          = (const float*)d_in[5];
    const float* b_in          = (const float*)d_in[6];
    const float* ln1_g         = (const float*)d_in[7];
    const float* ln1_b         = (const float*)d_in[8];
    const float* w_qkv         = (const float*)d_in[9];
    const float* b_qkv         = (const float*)d_in[10];
    const float* w_o           = (const float*)d_in[11];
    const float* b_o           = (const float*)d_in[12];
    const float* ln2_g         = (const float*)d_in[13];
    const float* ln2_b         = (const float*)d_in[14];
    const float* w_m1          = (const float*)d_in[15];
    const float* b_m1          = (const float*)d_in[16];
    const float* w_m2          = (const float*)d_in[17];
    const float* b_m2          = (const float*)d_in[18];
    const float* lnf_g         = (const float*)d_in[19];
    const float* lnf_b         = (const float*)d_in[20];
    const float* w_out         = (const float*)d_in[21];
    const float* b_out         = (const float*)d_in[22];
    float* out = (float*)d_out;

    (void)in_sizes; (void)n_in; (void)out_size;

    cudaFuncSetAttribute(attn_flash, cudaFuncAttributeMaxDynamicSharedMemorySize, AT_SMEM);
    cudaFuncSetAttribute(gemm_mma<1>, cudaFuncAttributeMaxDynamicSharedMemorySize, GEMM_SMEM);
    cudaFuncSetAttribute(gemm_mma<2>, cudaFuncAttributeMaxDynamicSharedMemorySize, GEMM_SMEM);
    cudaFuncSetAttribute(gemm_mma<3>, cudaFuncAttributeMaxDynamicSharedMemorySize, GEMM_SMEM);
    cudaFuncSetAttribute(gemm_mma<4>, cudaFuncAttributeMaxDynamicSharedMemorySize, GEMM_SMEM);

    float* px;
    bf16 *qh, *ql, *yh, *yl, *ah, *al, *mh, *ml;
    cudaGetSymbolAddress((void**)&px, g_x);
    cudaGetSymbolAddress((void**)&qh, g_qh);
    cudaGetSymbolAddress((void**)&ql, g_ql);
    cudaGetSymbolAddress((void**)&yh, g_yh);
    cudaGetSymbolAddress((void**)&yl, g_yl);
    cudaGetSymbolAddress((void**)&ah, g_ah);
    cudaGetSymbolAddress((void**)&al, g_al);
    cudaGetSymbolAddress((void**)&mh, g_mh);
    cudaGetSymbolAddress((void**)&ml, g_ml);
    bf16 *wqh, *wql, *woh, *wol, *w1h, *w1l, *w2h, *w2l;
    cudaGetSymbolAddress((void**)&wqh, g_wq_hi);
    cudaGetSymbolAddress((void**)&wql, g_wq_lo);
    cudaGetSymbolAddress((void**)&woh, g_wo_hi);
    cudaGetSymbolAddress((void**)&wol, g_wo_lo);
    cudaGetSymbolAddress((void**)&w1h, g_wm1_hi);
    cudaGetSymbolAddress((void**)&w1l, g_wm1_lo);
    cudaGetSymbolAddress((void**)&w2h, g_wm2_hi);
    cudaGetSymbolAddress((void**)&w2l, g_wm2_lo);

    int wtotal = NBLK * (WQ_E + WO_E + W1_E + W2_E);
    wprep_kernel<<<(wtotal + 255) / 256, 256>>>(w_qkv, w_o, w_m1, w_m2);

    bn_stats_kernel<<<16, 256>>>(inputs_scalar, inputs_v);
    seg_kernel<<<1, 256>>>(batch_idx);
    embed_ln_kernel<<<NT / 8, 256>>>(inputs_scalar, inputs_v, bn_gamma, bn_beta,
                                     w_in, b_in, ln1_g, ln1_b);

    for (int i = 0; i < NBLK; i++) {
        gemm_mma<3><<<dim3(3, NT / 64), 256, GEMM_SMEM>>>(
            yh, yl, wqh + (size_t)i * WQ_E, wql + (size_t)i * WQ_E,
            b_qkv + i * 3 * DD, nullptr, nullptr, qh, ql, 128, 384, nullptr, nullptr);
        attn_flash<<<dim3(GN, HN), 256, AT_SMEM>>>();
        gemm_mma<4><<<dim3(1, NT / 64), 256, GEMM_SMEM>>>(
            ah, al, woh + (size_t)i * WO_E, wol + (size_t)i * WO_E,
            b_o + i * DD, px, px, yh, yl, 128, 128,
            ln2_g + i * DD, ln2_b + i * DD);
        gemm_mma<2><<<dim3(4, NT / 64), 256, GEMM_SMEM>>>(
            yh, yl, w1h + (size_t)i * W1_E, w1l + (size_t)i * W1_E,
            b_m1 + i * 4 * DD, nullptr, nullptr, mh, ml, 128, 512, nullptr, nullptr);
        const float* ng = (i + 1 < NBLK) ? (ln1_g + (i + 1) * DD) : lnf_g;
        const float* nb = (i + 1 < NBLK) ? (ln1_b + (i + 1) * DD) : lnf_b;
        gemm_mma<4><<<dim3(1, NT / 64), 256, GEMM_SMEM>>>(
            mh, ml, w2h + (size_t)i * W2_E, w2l + (size_t)i * W2_E,
            b_m2 + i * DD, px, px, yh, yl, 512, 128, ng, nb);
    }

    out_kernel<<<NT, 128>>>(w_out, b_out, out);
}